// round 2
// baseline (speedup 1.0000x reference)
#include <cuda_runtime.h>
#include <cuda_bf16.h>

#define S_LEN  2048
#define H_DIM  2048
#define V_DIM  32000
#define NSEGC  16
#define R_DIM  256
#define TM_LEN 1024
#define NROWS  6144       /* 4094 main + 2 pad + 2048 math */
#define NCHUNK 250        /* V / 128 */
#define NSLICE 3
#define NEG_BIG (-1e30f)

/* ------------------------------------------------------------------ */
/* scratch (static __device__ — no allocation)                         */
/* ------------------------------------------------------------------ */
__device__ float     g_trans[2 * TM_LEN * H_DIM];       /* 16 MB */
__device__ float     g_inter[2 * NSEGC * 64 * R_DIM];   /*  2 MB */
__device__ float     g_m [NSLICE * NROWS];
__device__ float     g_l [NSLICE * NROWS];
__device__ float     g_ll[NSLICE * NROWS];
__device__ long long g_off[NROWS];
__device__ int       g_lab[NROWS];
__device__ int       g_flags[NROWS];

/* ------------------------------------------------------------------ */
/* packed f32x2 helpers (FFMA2 path — 2x fp32 FMA throughput)          */
/* ------------------------------------------------------------------ */
__device__ __forceinline__ unsigned long long pack2(float x) {
    unsigned long long r;
    asm("mov.b64 %0, {%1, %1};" : "=l"(r) : "f"(x));
    return r;
}
__device__ __forceinline__ void fma2(unsigned long long& d,
                                     unsigned long long a,
                                     unsigned long long b) {
    asm("fma.rn.f32x2 %0, %1, %2, %0;" : "+l"(d) : "l"(a), "l"(b));
}
__device__ __forceinline__ void unpack2(unsigned long long v, float& lo, float& hi) {
    asm("mov.b64 {%0, %1}, %2;" : "=f"(lo), "=f"(hi) : "l"(v));
}

/* ------------------------------------------------------------------ */
/* setup: row table (src offset, label, mask flags) + real_len         */
/* ------------------------------------------------------------------ */
__global__ void setup_kernel(const int* __restrict__ input_ids,
                             const int* __restrict__ attention_mask,
                             const int* __restrict__ starts,
                             const int* __restrict__ ends,
                             const int* __restrict__ math_labels,
                             const int* __restrict__ math_mask) {
    __shared__ int warpsum[8];
    __shared__ int s_rlen[2];
    int tid = threadIdx.x;

    for (int b = 0; b < 2; b++) {
        int v = 0;
        for (int s = tid; s < S_LEN; s += 256) v += attention_mask[b * S_LEN + s];
        #pragma unroll
        for (int m = 16; m; m >>= 1) v += __shfl_xor_sync(0xffffffffu, v, m);
        if ((tid & 31) == 0) warpsum[tid >> 5] = v;
        __syncthreads();
        if (tid == 0) {
            int t = 0;
            for (int w = 0; w < 8; w++) t += warpsum[w];
            s_rlen[b] = t;
        }
        __syncthreads();
    }

    for (int r = tid; r < NROWS; r += 256) {
        long long off; int lab; int fl = 0;
        if (r < 4094) {                       /* main rows: b = r/2047, s = r%2047 */
            int b = r / 2047;
            int s = r - b * 2047;
            off = (long long)(b * S_LEN + s) * H_DIM;
            lab = input_ids[b * S_LEN + s + 1];
            int st = starts[b], en = ends[b];
            if (s >= st - 1 && s <= en - 1) fl |= 1;          /* simple-talk */
            if (s >= en && s < s_rlen[b] - 1) fl |= 2;        /* final-answer */
        } else if (r < 4096) {                /* padding */
            off = 0; lab = 0; fl = 0;
        } else {                              /* math rows (into g_trans) */
            int idx = r - 4096;
            int b = idx >> 10, p = idx & 1023;
            off = (long long)(b * TM_LEN + p) * H_DIM;
            lab = math_labels[b * TM_LEN + p];
            fl  = math_mask[b * TM_LEN + p] ? 4 : 0;
        }
        g_off[r] = off; g_lab[r] = lab; g_flags[r] = fl;
    }
}

/* ------------------------------------------------------------------ */
/* M1: inter[b,seg][64,256] = gather(hidden) @ B_seg^T   (K = 2048)    */
/* ------------------------------------------------------------------ */
__global__ __launch_bounds__(256, 1)
void m1_kernel(const float* __restrict__ hidden,
               const int*   __restrict__ starts,
               const float* __restrict__ Bm) {
    __shared__ __align__(16) float a_s[64 * 33];
    __shared__ __align__(16) float b_s[32 * 260];
    int tid = threadIdx.x;
    int b   = blockIdx.x >> 4;
    int seg = blockIdx.x & 15;
    int st  = starts[b];
    const float* abase = hidden + (long long)(b * S_LEN + st + seg * 64) * H_DIM;
    const float* bbase = Bm + (long long)seg * R_DIM * H_DIM;

    int lr = tid >> 2;            /* 0..63 */
    int lk = (tid & 3) * 8;       /* 0,8,16,24 */
    int row0 = (tid >> 5) * 8;    /* 8 row groups */
    int col0 = (tid & 31) * 8;    /* 32 col groups */

    float acc[8][8];
    #pragma unroll
    for (int i = 0; i < 8; i++)
        #pragma unroll
        for (int j = 0; j < 8; j++) acc[i][j] = 0.f;

    for (int kt = 0; kt < H_DIM / 32; kt++) {
        int k0 = kt * 32;
        __syncthreads();
        {
            const float* ap = abase + (long long)lr * H_DIM + k0 + lk;
            float4 x0 = *(const float4*)ap;
            float4 x1 = *(const float4*)(ap + 4);
            float* d = a_s + lr * 33 + lk;
            d[0]=x0.x; d[1]=x0.y; d[2]=x0.z; d[3]=x0.w;
            d[4]=x1.x; d[5]=x1.y; d[6]=x1.z; d[7]=x1.w;
            #pragma unroll
            for (int q = 0; q < 4; q++) {
                int col = lr + q * 64;
                const float* bp = bbase + (long long)col * H_DIM + k0 + lk;
                float4 y0 = *(const float4*)bp;
                float4 y1 = *(const float4*)(bp + 4);
                float* e = b_s + lk * 260 + col;
                e[0*260]=y0.x; e[1*260]=y0.y; e[2*260]=y0.z; e[3*260]=y0.w;
                e[4*260]=y1.x; e[5*260]=y1.y; e[6*260]=y1.z; e[7*260]=y1.w;
            }
        }
        __syncthreads();
        #pragma unroll 8
        for (int kk = 0; kk < 32; kk++) {
            float ar[8];
            #pragma unroll
            for (int i = 0; i < 8; i++) ar[i] = a_s[(row0 + i) * 33 + kk];
            float4 w0 = *(const float4*)(b_s + kk * 260 + col0);
            float4 w1 = *(const float4*)(b_s + kk * 260 + col0 + 4);
            float br[8] = {w0.x, w0.y, w0.z, w0.w, w1.x, w1.y, w1.z, w1.w};
            #pragma unroll
            for (int i = 0; i < 8; i++)
                #pragma unroll
                for (int j = 0; j < 8; j++) acc[i][j] = fmaf(ar[i], br[j], acc[i][j]);
        }
    }
    float* out = g_inter + (long long)blockIdx.x * 64 * R_DIM;
    #pragma unroll
    for (int i = 0; i < 8; i++)
        #pragma unroll
        for (int j = 0; j < 8; j++)
            out[(row0 + i) * R_DIM + col0 + j] = acc[i][j];
}

/* ------------------------------------------------------------------ */
/* M2: trans[b,seg][64, 256-col block] = inter @ A_seg^T + bias  (K=256) */
/* ------------------------------------------------------------------ */
__global__ __launch_bounds__(256, 1)
void m2_kernel(const float* __restrict__ Am,
               const float* __restrict__ bias) {
    __shared__ __align__(16) float a_s[64 * 33];
    __shared__ __align__(16) float b_s[32 * 260];
    int tid = threadIdx.x;
    int bs = blockIdx.x;
    int b = bs >> 4, seg = bs & 15;
    int cb = blockIdx.y;                       /* 0..7 : h block of 256 */
    const float* abase = g_inter + (long long)bs * 64 * R_DIM;
    const float* bbase = Am + ((long long)seg * H_DIM + cb * 256) * R_DIM;

    int lr = tid >> 2;
    int lk = (tid & 3) * 8;
    int row0 = (tid >> 5) * 8;
    int col0 = (tid & 31) * 8;

    float acc[8][8];
    #pragma unroll
    for (int i = 0; i < 8; i++)
        #pragma unroll
        for (int j = 0; j < 8; j++) acc[i][j] = 0.f;

    for (int kt = 0; kt < R_DIM / 32; kt++) {
        int k0 = kt * 32;
        __syncthreads();
        {
            const float* ap = abase + (long long)lr * R_DIM + k0 + lk;
            float4 x0 = *(const float4*)ap;
            float4 x1 = *(const float4*)(ap + 4);
            float* d = a_s + lr * 33 + lk;
            d[0]=x0.x; d[1]=x0.y; d[2]=x0.z; d[3]=x0.w;
            d[4]=x1.x; d[5]=x1.y; d[6]=x1.z; d[7]=x1.w;
            #pragma unroll
            for (int q = 0; q < 4; q++) {
                int col = lr + q * 64;
                const float* bp = bbase + (long long)col * R_DIM + k0 + lk;
                float4 y0 = *(const float4*)bp;
                float4 y1 = *(const float4*)(bp + 4);
                float* e = b_s + lk * 260 + col;
                e[0*260]=y0.x; e[1*260]=y0.y; e[2*260]=y0.z; e[3*260]=y0.w;
                e[4*260]=y1.x; e[5*260]=y1.y; e[6*260]=y1.z; e[7*260]=y1.w;
            }
        }
        __syncthreads();
        #pragma unroll 8
        for (int kk = 0; kk < 32; kk++) {
            float ar[8];
            #pragma unroll
            for (int i = 0; i < 8; i++) ar[i] = a_s[(row0 + i) * 33 + kk];
            float4 w0 = *(const float4*)(b_s + kk * 260 + col0);
            float4 w1 = *(const float4*)(b_s + kk * 260 + col0 + 4);
            float br[8] = {w0.x, w0.y, w0.z, w0.w, w1.x, w1.y, w1.z, w1.w};
            #pragma unroll
            for (int i = 0; i < 8; i++)
                #pragma unroll
                for (int j = 0; j < 8; j++) acc[i][j] = fmaf(ar[i], br[j], acc[i][j]);
        }
    }
    #pragma unroll
    for (int i = 0; i < 8; i++) {
        long long orow = (long long)(b * TM_LEN + seg * 64 + row0 + i) * H_DIM;
        #pragma unroll
        for (int j = 0; j < 8; j++) {
            int h = cb * 256 + col0 + j;
            g_trans[orow + h] = acc[i][j] + bias[seg * H_DIM + h];
        }
    }
}

/* ------------------------------------------------------------------ */
/* CE: fused logits GEMM + online logsumexp + label gather             */
/* grid (48 row-blocks of 128, 3 V-slices), 256 threads               */
/* ------------------------------------------------------------------ */
__global__ __launch_bounds__(256, 1)
void ce_kernel(const float* __restrict__ hidden,
               const float* __restrict__ W) {
    __shared__ __align__(16) float sh_h[32 * 132];
    __shared__ __align__(16) float sh_w[32 * 132];
    __shared__ const float* s_ptr[128];
    __shared__ int s_lab[128];

    int tid   = threadIdx.x;
    int rb    = blockIdx.x;
    int slice = blockIdx.y;
    int row_t = tid >> 4;          /* 16 row groups of 8 */
    int col_t = tid & 15;          /* 16 col groups of 8 */
    int row0  = row_t * 8;
    int col0  = col_t * 8;
    int lrow  = tid >> 3;          /* 0..31 : loader row base  */
    int lkq   = (tid & 7) * 4;     /* 0,4,...,28 : loader k    */

    if (tid < 128) {
        int grow = rb * 128 + tid;
        long long off = g_off[grow];
        s_ptr[tid] = (grow < 4096 ? hidden : g_trans) + off;
        s_lab[tid] = g_lab[grow];
    }
    __syncthreads();

    const float* hrow[4];
    #pragma unroll
    for (int q = 0; q < 4; q++) hrow[q] = s_ptr[lrow + q * 32] + lkq;

    int lab[8];
    #pragma unroll
    for (int i = 0; i < 8; i++) lab[i] = s_lab[row0 + i];

    int c0 = (slice * NCHUNK) / NSLICE;
    int c1 = ((slice + 1) * NCHUNK) / NSLICE;

    float m_run[8], l_run[8], ll[8];
    #pragma unroll
    for (int i = 0; i < 8; i++) { m_run[i] = NEG_BIG; l_run[i] = 0.f; ll[i] = NEG_BIG; }

    for (int c = c0; c < c1; c++) {
        int vbase = c * 128;
        const float* wrow[4];
        #pragma unroll
        for (int q = 0; q < 4; q++)
            wrow[q] = W + (long long)(vbase + lrow + q * 32) * H_DIM + lkq;

        unsigned long long acc[8][4];
        #pragma unroll
        for (int i = 0; i < 8; i++)
            #pragma unroll
            for (int j = 0; j < 4; j++) acc[i][j] = 0ull;

        /* prefetch tile 0 */
        float4 ph[4], pw[4];
        #pragma unroll
        for (int q = 0; q < 4; q++) {
            ph[q] = *(const float4*)(hrow[q]);
            pw[q] = *(const float4*)(wrow[q]);
        }

        for (int kt = 0; kt < 64; kt++) {
            __syncthreads();
            #pragma unroll
            for (int q = 0; q < 4; q++) {
                int r = lrow + q * 32;
                float* hh = sh_h + lkq * 132 + r;
                hh[0]   = ph[q].x; hh[132] = ph[q].y;
                hh[264] = ph[q].z; hh[396] = ph[q].w;
                float* ww = sh_w + lkq * 132 + r;
                ww[0]   = pw[q].x; ww[132] = pw[q].y;
                ww[264] = pw[q].z; ww[396] = pw[q].w;
            }
            __syncthreads();
            if (kt < 63) {
                int k0 = (kt + 1) * 32;
                #pragma unroll
                for (int q = 0; q < 4; q++) {
                    ph[q] = *(const float4*)(hrow[q] + k0);
                    pw[q] = *(const float4*)(wrow[q] + k0);
                }
            }
            #pragma unroll 8
            for (int kk = 0; kk < 32; kk++) {
                float4 ha = *(const float4*)(sh_h + kk * 132 + row0);
                float4 hb = *(const float4*)(sh_h + kk * 132 + row0 + 4);
                ulonglong2 wa = *(const ulonglong2*)(sh_w + kk * 132 + col0);
                ulonglong2 wb = *(const ulonglong2*)(sh_w + kk * 132 + col0 + 4);
                unsigned long long hq[8];
                hq[0] = pack2(ha.x); hq[1] = pack2(ha.y);
                hq[2] = pack2(ha.z); hq[3] = pack2(ha.w);
                hq[4] = pack2(hb.x); hq[5] = pack2(hb.y);
                hq[6] = pack2(hb.z); hq[7] = pack2(hb.w);
                #pragma unroll
                for (int i = 0; i < 8; i++) {
                    fma2(acc[i][0], hq[i], wa.x);
                    fma2(acc[i][1], hq[i], wa.y);
                    fma2(acc[i][2], hq[i], wb.x);
                    fma2(acc[i][3], hq[i], wb.y);
                }
            }
        }

        /* online-softmax epilogue for this 128-col chunk */
        #pragma unroll
        for (int i = 0; i < 8; i++) {
            float v[8];
            unpack2(acc[i][0], v[0], v[1]);
            unpack2(acc[i][1], v[2], v[3]);
            unpack2(acc[i][2], v[4], v[5]);
            unpack2(acc[i][3], v[6], v[7]);
            float cm = v[0];
            #pragma unroll
            for (int j = 1; j < 8; j++) cm = fmaxf(cm, v[j]);
            #pragma unroll
            for (int m = 1; m < 16; m <<= 1)
                cm = fmaxf(cm, __shfl_xor_sync(0xffffffffu, cm, m));
            float mn = fmaxf(m_run[i], cm);
            float ssum = 0.f;
            #pragma unroll
            for (int j = 0; j < 8; j++) ssum += __expf(v[j] - mn);
            #pragma unroll
            for (int m = 1; m < 16; m <<= 1)
                ssum += __shfl_xor_sync(0xffffffffu, ssum, m);
            l_run[i] = l_run[i] * __expf(m_run[i] - mn) + ssum;
            m_run[i] = mn;
            int vb = vbase + col0;
            #pragma unroll
            for (int j = 0; j < 8; j++)
                if (vb + j == lab[i]) ll[i] = v[j];
        }
    }

    /* write per-slice partials */
    #pragma unroll
    for (int i = 0; i < 8; i++) {
        float x = ll[i];
        #pragma unroll
        for (int m = 1; m < 16; m <<= 1)
            x = fmaxf(x, __shfl_xor_sync(0xffffffffu, x, m));
        if (col_t == 0) {
            int grow = rb * 128 + row0 + i;
            g_m [slice * NROWS + grow] = m_run[i];
            g_l [slice * NROWS + grow] = l_run[i];
            g_ll[slice * NROWS + grow] = x;
        }
    }
}

/* ------------------------------------------------------------------ */
/* final: merge slices -> nll -> masked means -> 4 outputs             */
/* ------------------------------------------------------------------ */
__global__ void reduce_kernel(float* __restrict__ out, int out_size) {
    __shared__ float sred[6][8];
    int tid = threadIdx.x;
    float vals[6] = {0.f, 0.f, 0.f, 0.f, 0.f, 0.f}; /* s_m,c_m,s_st,c_st,s_fa,c_fa */

    for (int r = tid; r < NROWS; r += 256) {
        int fl = g_flags[r];
        if (!fl) continue;
        float m0 = g_m[r], m1 = g_m[NROWS + r], m2 = g_m[2 * NROWS + r];
        float m = fmaxf(m0, fmaxf(m1, m2));
        float l = g_l[r] * __expf(m0 - m)
                + g_l[NROWS + r] * __expf(m1 - m)
                + g_l[2 * NROWS + r] * __expf(m2 - m);
        float llv = fmaxf(g_ll[r], fmaxf(g_ll[NROWS + r], g_ll[2 * NROWS + r]));
        float nll = m + logf(l) - llv;
        if (fl & 4) { vals[0] += nll; vals[1] += 1.f; }
        if (fl & 1) { vals[2] += nll; vals[3] += 1.f; }
        if (fl & 2) { vals[4] += nll; vals[5] += 1.f; }
    }
    #pragma unroll
    for (int k = 0; k < 6; k++) {
        float v = vals[k];
        #pragma unroll
        for (int m = 16; m; m >>= 1) v += __shfl_xor_sync(0xffffffffu, v, m);
        if ((tid & 31) == 0) sred[k][tid >> 5] = v;
    }
    __syncthreads();
    if (tid == 0) {
        float tot[6];
        #pragma unroll
        for (int k = 0; k < 6; k++) {
            float a = 0.f;
            for (int w = 0; w < 8; w++) a += sred[k][w];
            tot[k] = a;
        }
        float math_loss = tot[0] / fmaxf(tot[1], 1.f);
        float st_loss   = tot[2] / fmaxf(tot[3], 1.f);
        float fa_loss   = tot[4] / fmaxf(tot[5], 1.f);
        float total = 0.5f * math_loss + 0.5f * st_loss + 0.4f * fa_loss;
        if (out_size > 0) out[0] = total;
        if (out_size > 1) out[1] = math_loss;
        if (out_size > 2) out[2] = st_loss;
        if (out_size > 3) out[3] = fa_loss;
        for (int i = 4; i < out_size; i++) out[i] = 0.f;
    }
}

/* ------------------------------------------------------------------ */
extern "C" void kernel_launch(void* const* d_in, const int* in_sizes, int n_in,
                              void* d_out, int out_size) {
    const float* hidden   = (const float*)d_in[0];
    const int*   ids      = (const int*)d_in[1];
    const int*   amask    = (const int*)d_in[2];
    const int*   starts   = (const int*)d_in[3];
    const int*   ends     = (const int*)d_in[4];
    const int*   mlab     = (const int*)d_in[5];
    const int*   mmask    = (const int*)d_in[6];
    /* d_in[7] = math_lengths (unused) */
    const float* Amat     = (const float*)d_in[8];
    const float* Bmat     = (const float*)d_in[9];
    const float* bias     = (const float*)d_in[10];
    const float* W        = (const float*)d_in[11];
    float* out = (float*)d_out;

    setup_kernel<<<1, 256>>>(ids, amask, starts, ends, mlab, mmask);
    m1_kernel<<<32, 256>>>(hidden, starts, Bmat);
    m2_kernel<<<dim3(32, 8), 256>>>(Amat, bias);
    ce_kernel<<<dim3(48, NSLICE), 256>>>(hidden, W);
    reduce_kernel<<<1, 256>>>(out, out_size);
}

// round 4
// speedup vs baseline: 3.0186x; 3.0186x over previous
#include <cuda_runtime.h>
#include <cuda_bf16.h>
#include <cstdint>

#define S_LEN  2048
#define H_DIM  2048
#define V_DIM  32000
#define NSEGC  16
#define R_DIM  256
#define TM_LEN 1024
#define NROWS  6144       /* 4094 main + 2 pad + 2048 math */
#define NCHUNK 250        /* V / 128 */
#define NSLICE 3
#define NEG_BIG (-1e30f)

/* CE tiling */
#define KC      32        /* K-chunk staged in smem */
#define NKC     64        /* 2048 / 32 */
#define PADS    36        /* floats per smem row (stride) -> conflict-free frags */
#define SM_PTR  0         /* 128 x u64  = 1024 B */
#define SM_LAB  1024      /* 128 x int  = 512 B  */
#define SM_CMB  1536      /* 6 x 128 f  = 3072 B */
#define SM_A    4736      /* 2 x 128 x 36 x 4 = 36864 B */
#define SM_B    41600     /* 2 x 128 x 36 x 4 = 36864 B */
#define SMEM_CE (SM_B + 36864)   /* 78464 B */

/* ------------------------------------------------------------------ */
__device__ float     g_trans[2 * TM_LEN * H_DIM];       /* 16 MB */
__device__ float     g_inter[2 * NSEGC * 64 * R_DIM];   /*  2 MB */
__device__ float     g_m [NSLICE * NROWS];
__device__ float     g_l [NSLICE * NROWS];
__device__ float     g_ll[NSLICE * NROWS];
__device__ long long g_off[NROWS];
__device__ int       g_lab[NROWS];
__device__ int       g_flags[NROWS];

/* ------------------------------------------------------------------ */
/* helpers                                                             */
/* ------------------------------------------------------------------ */
__device__ __forceinline__ unsigned long long pack2(float x) {
    unsigned long long r;
    asm("mov.b64 %0, {%1, %1};" : "=l"(r) : "f"(x));
    return r;
}
__device__ __forceinline__ void fma2(unsigned long long& d,
                                     unsigned long long a,
                                     unsigned long long b) {
    asm("fma.rn.f32x2 %0, %1, %2, %0;" : "+l"(d) : "l"(a), "l"(b));
}
__device__ __forceinline__ void unpack2(unsigned long long v, float& lo, float& hi) {
    asm("mov.b64 {%0, %1}, %2;" : "=f"(lo), "=f"(hi) : "l"(v));
}
__device__ __forceinline__ uint32_t f2tf(float x) {
    uint32_t r;
    asm("cvt.rna.tf32.f32 %0, %1;" : "=r"(r) : "f"(x));
    return r;
}
__device__ __forceinline__ void mma_tf32(float* c, const uint32_t* a, const uint32_t* b) {
    asm("mma.sync.aligned.m16n8k8.row.col.f32.tf32.tf32.f32 "
        "{%0,%1,%2,%3}, {%4,%5,%6,%7}, {%8,%9}, {%0,%1,%2,%3};"
        : "+f"(c[0]), "+f"(c[1]), "+f"(c[2]), "+f"(c[3])
        : "r"(a[0]), "r"(a[1]), "r"(a[2]), "r"(a[3]), "r"(b[0]), "r"(b[1]));
}
__device__ __forceinline__ uint32_t smem_u32(const void* p) {
    uint32_t a;
    asm("{ .reg .u64 t; cvta.to.shared.u64 t, %1; cvt.u32.u64 %0, t; }"
        : "=r"(a) : "l"(p));
    return a;
}
#define CP_ASYNC16(dst, src) \
    asm volatile("cp.async.cg.shared.global [%0], [%1], 16;" \
                 :: "r"(dst), "l"(src) : "memory")
#define CP_COMMIT() asm volatile("cp.async.commit_group;" ::: "memory")
#define CP_WAIT1()  asm volatile("cp.async.wait_group 1;" ::: "memory")
#define CP_WAIT0()  asm volatile("cp.async.wait_group 0;" ::: "memory")

/* ------------------------------------------------------------------ */
/* setup: row table                                                    */
/* ------------------------------------------------------------------ */
__global__ void setup_kernel(const int* __restrict__ input_ids,
                             const int* __restrict__ attention_mask,
                             const int* __restrict__ starts,
                             const int* __restrict__ ends,
                             const int* __restrict__ math_labels,
                             const int* __restrict__ math_mask) {
    __shared__ int warpsum[8];
    __shared__ int s_rlen[2];
    int tid = threadIdx.x;

    for (int b = 0; b < 2; b++) {
        int v = 0;
        for (int s = tid; s < S_LEN; s += 256) v += attention_mask[b * S_LEN + s];
        #pragma unroll
        for (int m = 16; m; m >>= 1) v += __shfl_xor_sync(0xffffffffu, v, m);
        if ((tid & 31) == 0) warpsum[tid >> 5] = v;
        __syncthreads();
        if (tid == 0) {
            int t = 0;
            for (int w = 0; w < 8; w++) t += warpsum[w];
            s_rlen[b] = t;
        }
        __syncthreads();
    }

    for (int r = tid; r < NROWS; r += 256) {
        long long off; int lab; int fl = 0;
        if (r < 4094) {
            int b = r / 2047;
            int s = r - b * 2047;
            off = (long long)(b * S_LEN + s) * H_DIM;
            lab = input_ids[b * S_LEN + s + 1];
            int st = starts[b], en = ends[b];
            if (s >= st - 1 && s <= en - 1) fl |= 1;
            if (s >= en && s < s_rlen[b] - 1) fl |= 2;
        } else if (r < 4096) {
            off = 0; lab = 0; fl = 0;
        } else {
            int idx = r - 4096;
            int b = idx >> 10, p = idx & 1023;
            off = (long long)(b * TM_LEN + p) * H_DIM;
            lab = math_labels[b * TM_LEN + p];
            fl  = math_mask[b * TM_LEN + p] ? 4 : 0;
        }
        g_off[r] = off; g_lab[r] = lab; g_flags[r] = fl;
    }
}

/* ------------------------------------------------------------------ */
/* M1: inter = gather(hidden) @ B_seg^T  (K=2048)                      */
/* ------------------------------------------------------------------ */
__global__ __launch_bounds__(256, 1)
void m1_kernel(const float* __restrict__ hidden,
               const int*   __restrict__ starts,
               const float* __restrict__ Bm) {
    __shared__ __align__(16) float a_s[64 * 33];
    __shared__ __align__(16) float b_s[32 * 260];
    int tid = threadIdx.x;
    int b   = blockIdx.x >> 4;
    int seg = blockIdx.x & 15;
    int st  = starts[b];
    const float* abase = hidden + (long long)(b * S_LEN + st + seg * 64) * H_DIM;
    const float* bbase = Bm + (long long)seg * R_DIM * H_DIM;

    int lr = tid >> 2;
    int lk = (tid & 3) * 8;
    int row0 = (tid >> 5) * 8;
    int col0 = (tid & 31) * 8;

    unsigned long long acc[8][4];
    #pragma unroll
    for (int i = 0; i < 8; i++)
        #pragma unroll
        for (int j = 0; j < 4; j++) acc[i][j] = 0ull;

    for (int kt = 0; kt < H_DIM / 32; kt++) {
        int k0 = kt * 32;
        __syncthreads();
        {
            const float* ap = abase + (long long)lr * H_DIM + k0 + lk;
            float4 x0 = *(const float4*)ap;
            float4 x1 = *(const float4*)(ap + 4);
            float* d = a_s + lr * 33 + lk;
            d[0]=x0.x; d[1]=x0.y; d[2]=x0.z; d[3]=x0.w;
            d[4]=x1.x; d[5]=x1.y; d[6]=x1.z; d[7]=x1.w;
            #pragma unroll
            for (int q = 0; q < 4; q++) {
                int col = lr + q * 64;
                const float* bp = bbase + (long long)col * H_DIM + k0 + lk;
                float4 y0 = *(const float4*)bp;
                float4 y1 = *(const float4*)(bp + 4);
                float* e = b_s + lk * 260 + col;
                e[0*260]=y0.x; e[1*260]=y0.y; e[2*260]=y0.z; e[3*260]=y0.w;
                e[4*260]=y1.x; e[5*260]=y1.y; e[6*260]=y1.z; e[7*260]=y1.w;
            }
        }
        __syncthreads();
        #pragma unroll 8
        for (int kk = 0; kk < 32; kk++) {
            float ar[8];
            #pragma unroll
            for (int i = 0; i < 8; i++) ar[i] = a_s[(row0 + i) * 33 + kk];
            ulonglong2 wa = *(const ulonglong2*)(b_s + kk * 260 + col0);
            ulonglong2 wb = *(const ulonglong2*)(b_s + kk * 260 + col0 + 4);
            #pragma unroll
            for (int i = 0; i < 8; i++) {
                unsigned long long h = pack2(ar[i]);
                fma2(acc[i][0], h, wa.x);
                fma2(acc[i][1], h, wa.y);
                fma2(acc[i][2], h, wb.x);
                fma2(acc[i][3], h, wb.y);
            }
        }
    }
    float* out = g_inter + (long long)blockIdx.x * 64 * R_DIM;
    #pragma unroll
    for (int i = 0; i < 8; i++) {
        float v[8];
        unpack2(acc[i][0], v[0], v[1]);
        unpack2(acc[i][1], v[2], v[3]);
        unpack2(acc[i][2], v[4], v[5]);
        unpack2(acc[i][3], v[6], v[7]);
        #pragma unroll
        for (int j = 0; j < 8; j++)
            out[(row0 + i) * R_DIM + col0 + j] = v[j];
    }
}

/* ------------------------------------------------------------------ */
/* M2: trans = inter @ A_seg^T + bias  (K=256)                         */
/* ------------------------------------------------------------------ */
__global__ __launch_bounds__(256, 1)
void m2_kernel(const float* __restrict__ Am,
               const float* __restrict__ bias) {
    __shared__ __align__(16) float a_s[64 * 33];
    __shared__ __align__(16) float b_s[32 * 260];
    int tid = threadIdx.x;
    int bs = blockIdx.x;
    int b = bs >> 4, seg = bs & 15;
    int cb = blockIdx.y;
    const float* abase = g_inter + (long long)bs * 64 * R_DIM;
    const float* bbase = Am + ((long long)seg * H_DIM + cb * 256) * R_DIM;

    int lr = tid >> 2;
    int lk = (tid & 3) * 8;
    int row0 = (tid >> 5) * 8;
    int col0 = (tid & 31) * 8;

    unsigned long long acc[8][4];
    #pragma unroll
    for (int i = 0; i < 8; i++)
        #pragma unroll
        for (int j = 0; j < 4; j++) acc[i][j] = 0ull;

    for (int kt = 0; kt < R_DIM / 32; kt++) {
        int k0 = kt * 32;
        __syncthreads();
        {
            const float* ap = abase + (long long)lr * R_DIM + k0 + lk;
            float4 x0 = *(const float4*)ap;
            float4 x1 = *(const float4*)(ap + 4);
            float* d = a_s + lr * 33 + lk;
            d[0]=x0.x; d[1]=x0.y; d[2]=x0.z; d[3]=x0.w;
            d[4]=x1.x; d[5]=x1.y; d[6]=x1.z; d[7]=x1.w;
            #pragma unroll
            for (int q = 0; q < 4; q++) {
                int col = lr + q * 64;
                const float* bp = bbase + (long long)col * R_DIM + k0 + lk;
                float4 y0 = *(const float4*)bp;
                float4 y1 = *(const float4*)(bp + 4);
                float* e = b_s + lk * 260 + col;
                e[0*260]=y0.x; e[1*260]=y0.y; e[2*260]=y0.z; e[3*260]=y0.w;
                e[4*260]=y1.x; e[5*260]=y1.y; e[6*260]=y1.z; e[7*260]=y1.w;
            }
        }
        __syncthreads();
        #pragma unroll 8
        for (int kk = 0; kk < 32; kk++) {
            float ar[8];
            #pragma unroll
            for (int i = 0; i < 8; i++) ar[i] = a_s[(row0 + i) * 33 + kk];
            ulonglong2 wa = *(const ulonglong2*)(b_s + kk * 260 + col0);
            ulonglong2 wb = *(const ulonglong2*)(b_s + kk * 260 + col0 + 4);
            #pragma unroll
            for (int i = 0; i < 8; i++) {
                unsigned long long h = pack2(ar[i]);
                fma2(acc[i][0], h, wa.x);
                fma2(acc[i][1], h, wa.y);
                fma2(acc[i][2], h, wb.x);
                fma2(acc[i][3], h, wb.y);
            }
        }
    }
    #pragma unroll
    for (int i = 0; i < 8; i++) {
        long long orow = (long long)(b * TM_LEN + seg * 64 + row0 + i) * H_DIM;
        float v[8];
        unpack2(acc[i][0], v[0], v[1]);
        unpack2(acc[i][1], v[2], v[3]);
        unpack2(acc[i][2], v[4], v[5]);
        unpack2(acc[i][3], v[6], v[7]);
        #pragma unroll
        for (int j = 0; j < 8; j++) {
            int h = cb * 256 + col0 + j;
            g_trans[orow + h] = v[j] + bias[seg * H_DIM + h];
        }
    }
}

/* ------------------------------------------------------------------ */
/* CE: mma.sync tf32 GEMM (128x128 block, K=2048) + online logsumexp   */
/* grid (48 row-blocks, 3 V-slices), 256 threads = 8 warps (4m x 2n)   */
/* ------------------------------------------------------------------ */
__global__ __launch_bounds__(256, 1)
void ce_mma_kernel(const float* __restrict__ hidden,
                   const float* __restrict__ W) {
    extern __shared__ __align__(16) char smem[];
    unsigned long long* s_ptr = (unsigned long long*)(smem + SM_PTR);
    int*   s_lab = (int*)(smem + SM_LAB);
    float* s_cmb = (float*)(smem + SM_CMB);
    float* sA    = (float*)(smem + SM_A);
    float* sB    = (float*)(smem + SM_B);
    uint32_t sA_u = smem_u32(sA);
    uint32_t sB_u = smem_u32(sB);

    int tid   = threadIdx.x;
    int rb    = blockIdx.x;
    int slice = blockIdx.y;
    int wid   = tid >> 5, lane = tid & 31;
    int warp_m = wid & 3;           /* 4 warps down M: 32 rows each */
    int warp_n = wid >> 2;          /* 2 warps across N: 64 cols each */
    int g  = lane >> 2;             /* groupID 0..7 */
    int tq = lane & 3;              /* thread-in-group 0..3 */

    if (tid < 128) {
        int grow = rb * 128 + tid;
        long long off = g_off[grow];
        const float* p = (grow < 4096 ? hidden : g_trans) + off;
        s_ptr[tid] = (unsigned long long)__cvta_generic_to_global((void*)p);
        s_lab[tid] = g_lab[grow];
    }
    __syncthreads();

    /* loader assignment: 4 iterations x 256 threads = 1024 16B-chunks */
    int arow[4], aq[4];
    unsigned long long asrc[4];
    #pragma unroll
    for (int t = 0; t < 4; t++) {
        int idx = t * 256 + tid;
        arow[t] = idx >> 3;
        aq[t]   = idx & 7;
        asrc[t] = s_ptr[arow[t]] + (unsigned long long)(aq[t] * 16);
    }

    /* per-thread row-state labels: (mt, h) -> row */
    int labr[2][2];
    #pragma unroll
    for (int mt = 0; mt < 2; mt++)
        #pragma unroll
        for (int h = 0; h < 2; h++)
            labr[mt][h] = s_lab[warp_m * 32 + mt * 16 + h * 8 + g];

    int c0 = (slice * NCHUNK) / NSLICE;
    int c1 = ((slice + 1) * NCHUNK) / NSLICE;

    float m_run[2][2], l_run[2][2], ll[2][2];
    #pragma unroll
    for (int mt = 0; mt < 2; mt++)
        #pragma unroll
        for (int h = 0; h < 2; h++) {
            m_run[mt][h] = NEG_BIG; l_run[mt][h] = 0.f; ll[mt][h] = NEG_BIG;
        }

    for (int c = c0; c < c1; c++) {
        int vbase = c * 128;

        float acc[2][8][4];
        #pragma unroll
        for (int mt = 0; mt < 2; mt++)
            #pragma unroll
            for (int nt = 0; nt < 8; nt++)
                #pragma unroll
                for (int j = 0; j < 4; j++) acc[mt][nt][j] = 0.f;

        /* stage loader (cp.async) */
        auto load_stage = [&](int kc) {
            int buf = kc & 1;
            uint32_t da = sA_u + (uint32_t)buf * 18432;
            uint32_t db = sB_u + (uint32_t)buf * 18432;
            unsigned long long koff = (unsigned long long)(kc * KC * 4);
            #pragma unroll
            for (int t = 0; t < 4; t++) {
                uint32_t dst = da + (uint32_t)(arow[t] * (PADS * 4) + aq[t] * 16);
                CP_ASYNC16(dst, (const void*)(asrc[t] + koff));
            }
            #pragma unroll
            for (int t = 0; t < 4; t++) {
                int idx = t * 256 + tid;
                int col = idx >> 3, q = idx & 7;
                const float* src = W + (long long)(vbase + col) * H_DIM + kc * KC + q * 4;
                uint32_t dst = db + (uint32_t)(col * (PADS * 4) + q * 16);
                CP_ASYNC16(dst, (const void*)__cvta_generic_to_global((void*)src));
            }
            CP_COMMIT();
        };

        load_stage(0);
        for (int kc = 0; kc < NKC; kc++) {
            int buf = kc & 1;
            if (kc + 1 < NKC) { load_stage(kc + 1); CP_WAIT1(); }
            else              { CP_WAIT0(); }
            __syncthreads();

            const float* tA = sA + buf * (128 * PADS) + (warp_m * 32) * PADS;
            const float* tB = sB + buf * (128 * PADS) + (warp_n * 64) * PADS;

            #pragma unroll
            for (int ks = 0; ks < 4; ks++) {
                int k0 = ks * 8;
                uint32_t af[2][4];
                #pragma unroll
                for (int mt = 0; mt < 2; mt++) {
                    const float* ab = tA + (mt * 16 + g) * PADS + k0 + tq;
                    af[mt][0] = f2tf(ab[0]);
                    af[mt][1] = f2tf(ab[8 * PADS]);
                    af[mt][2] = f2tf(ab[4]);
                    af[mt][3] = f2tf(ab[8 * PADS + 4]);
                }
                #pragma unroll
                for (int nt = 0; nt < 8; nt++) {
                    const float* bb = tB + (nt * 8 + g) * PADS + k0 + tq;
                    uint32_t bf[2];
                    bf[0] = f2tf(bb[0]);
                    bf[1] = f2tf(bb[4]);
                    mma_tf32(acc[0][nt], af[0], bf);
                    mma_tf32(acc[1][nt], af[1], bf);
                }
            }
            __syncthreads();
        }

        /* epilogue: online logsumexp for this 128-col chunk */
        #pragma unroll
        for (int mt = 0; mt < 2; mt++) {
            #pragma unroll
            for (int h = 0; h < 2; h++) {
                float cm = NEG_BIG;
                #pragma unroll
                for (int nt = 0; nt < 8; nt++) {
                    cm = fmaxf(cm, acc[mt][nt][2 * h]);
                    cm = fmaxf(cm, acc[mt][nt][2 * h + 1]);
                }
                cm = fmaxf(cm, __shfl_xor_sync(0xffffffffu, cm, 1));
                cm = fmaxf(cm, __shfl_xor_sync(0xffffffffu, cm, 2));
                float mn = fmaxf(m_run[mt][h], cm);
                float ssum = 0.f;
                int cbase = vbase + warp_n * 64 + 2 * tq;
                int lb = labr[mt][h];
                #pragma unroll
                for (int nt = 0; nt < 8; nt++) {
                    float v0 = acc[mt][nt][2 * h];
                    float v1 = acc[mt][nt][2 * h + 1];
                    ssum += __expf(v0 - mn) + __expf(v1 - mn);
                    int cc = cbase + nt * 8;
                    if (cc == lb)     ll[mt][h] = v0;
                    if (cc + 1 == lb) ll[mt][h] = v1;
                }
                ssum += __shfl_xor_sync(0xffffffffu, ssum, 1);
                ssum += __shfl_xor_sync(0xffffffffu, ssum, 2);
                l_run[mt][h] = l_run[mt][h] * __expf(m_run[mt][h] - mn) + ssum;
                m_run[mt][h] = mn;
            }
        }
    }

    /* combine the two warp_n halves via smem, write per-slice partials */
    #pragma unroll
    for (int mt = 0; mt < 2; mt++) {
        #pragma unroll
        for (int h = 0; h < 2; h++) {
            float lv = ll[mt][h];
            lv = fmaxf(lv, __shfl_xor_sync(0xffffffffu, lv, 1));
            lv = fmaxf(lv, __shfl_xor_sync(0xffffffffu, lv, 2));
            if (tq == 0) {
                int row = warp_m * 32 + mt * 16 + h * 8 + g;
                s_cmb[(warp_n * 3 + 0) * 128 + row] = m_run[mt][h];
                s_cmb[(warp_n * 3 + 1) * 128 + row] = l_run[mt][h];
                s_cmb[(warp_n * 3 + 2) * 128 + row] = lv;
            }
        }
    }
    __syncthreads();
    if (tid < 128) {
        int row = tid;
        float ma = s_cmb[row],       la = s_cmb[128 + row], lla = s_cmb[256 + row];
        float mb = s_cmb[384 + row], lb = s_cmb[512 + row], llb = s_cmb[640 + row];
        float m = fmaxf(ma, mb);
        float l = la * __expf(ma - m) + lb * __expf(mb - m);
        float llv = fmaxf(lla, llb);
        int grow = rb * 128 + row;
        g_m [slice * NROWS + grow] = m;
        g_l [slice * NROWS + grow] = l;
        g_ll[slice * NROWS + grow] = llv;
    }
}

/* ------------------------------------------------------------------ */
/* final: merge slices -> nll -> masked means -> 4 outputs             */
/* ------------------------------------------------------------------ */
__global__ void reduce_kernel(float* __restrict__ out, int out_size) {
    __shared__ float sred[6][8];
    int tid = threadIdx.x;
    float vals[6] = {0.f, 0.f, 0.f, 0.f, 0.f, 0.f};

    for (int r = tid; r < NROWS; r += 256) {
        int fl = g_flags[r];
        if (!fl) continue;
        float m0 = g_m[r], m1 = g_m[NROWS + r], m2 = g_m[2 * NROWS + r];
        float m = fmaxf(m0, fmaxf(m1, m2));
        float l = g_l[r] * __expf(m0 - m)
                + g_l[NROWS + r] * __expf(m1 - m)
                + g_l[2 * NROWS + r] * __expf(m2 - m);
        float llv = fmaxf(g_ll[r], fmaxf(g_ll[NROWS + r], g_ll[2 * NROWS + r]));
        float nll = m + logf(l) - llv;
        if (fl & 4) { vals[0] += nll; vals[1] += 1.f; }
        if (fl & 1) { vals[2] += nll; vals[3] += 1.f; }
        if (fl & 2) { vals[4] += nll; vals[5] += 1.f; }
    }
    #pragma unroll
    for (int k = 0; k < 6; k++) {
        float v = vals[k];
        #pragma unroll
        for (int m = 16; m; m >>= 1) v += __shfl_xor_sync(0xffffffffu, v, m);
        if ((tid & 31) == 0) sred[k][tid >> 5] = v;
    }
    __syncthreads();
    if (tid == 0) {
        float tot[6];
        #pragma unroll
        for (int k = 0; k < 6; k++) {
            float a = 0.f;
            for (int w = 0; w < 8; w++) a += sred[k][w];
            tot[k] = a;
        }
        float math_loss = tot[0] / fmaxf(tot[1], 1.f);
        float st_loss   = tot[2] / fmaxf(tot[3], 1.f);
        float fa_loss   = tot[4] / fmaxf(tot[5], 1.f);
        float total = 0.5f * math_loss + 0.5f * st_loss + 0.4f * fa_loss;
        if (out_size > 0) out[0] = total;
        if (out_size > 1) out[1] = math_loss;
        if (out_size > 2) out[2] = st_loss;
        if (out_size > 3) out[3] = fa_loss;
        for (int i = 4; i < out_size; i++) out[i] = 0.f;
    }
}

/* ------------------------------------------------------------------ */
extern "C" void kernel_launch(void* const* d_in, const int* in_sizes, int n_in,
                              void* d_out, int out_size) {
    const float* hidden   = (const float*)d_in[0];
    const int*   ids      = (const int*)d_in[1];
    const int*   amask    = (const int*)d_in[2];
    const int*   starts   = (const int*)d_in[3];
    const int*   ends     = (const int*)d_in[4];
    const int*   mlab     = (const int*)d_in[5];
    const int*   mmask    = (const int*)d_in[6];
    const float* Amat     = (const float*)d_in[8];
    const float* Bmat     = (const float*)d_in[9];
    const float* bias     = (const float*)d_in[10];
    const float* W        = (const float*)d_in[11];
    float* out = (float*)d_out;

    static int smem_set = 0;
    if (!smem_set) {
        cudaFuncSetAttribute(ce_mma_kernel,
                             cudaFuncAttributeMaxDynamicSharedMemorySize, SMEM_CE);
        smem_set = 1;
    }

    setup_kernel<<<1, 256>>>(ids, amask, starts, ends, mlab, mmask);
    m1_kernel<<<32, 256>>>(hidden, starts, Bmat);
    m2_kernel<<<dim3(32, 8), 256>>>(Amat, bias);
    ce_mma_kernel<<<dim3(48, NSLICE), 256, SMEM_CE>>>(hidden, W);
    reduce_kernel<<<1, 256>>>(out, out_size);
}

// round 5
// speedup vs baseline: 6.6090x; 2.1894x over previous
#include <cuda_runtime.h>
#include <cuda_bf16.h>
#include <cstdint>

#define S_LEN  2048
#define H_DIM  2048
#define V_DIM  32000
#define NSEGC  16
#define R_DIM  256
#define TM_LEN 1024
#define NROWS  6144       /* 4094 main + 2 pad + 2048 math */
#define NSLICE 3
#define NEG_BIG (-1e30f)

/* CE tiling: CTA 128x256, warps 2m x 4n, warp tile 64x64, bf16 k-chunk 64 */
#define BM     128
#define BN     256
#define NPASS  125        /* V / 256 */
#define KC     64
#define NKC    32         /* 2048/64 */
#define STG    3
#define A_STG  18432      /* 128 rows x 144B (72 bf16 padded) */
#define B_STG  36864      /* 256 rows x 144B */
#define SM_LAB 0          /* 128 int */
#define SM_CMB 512        /* 4 x 3 x 128 f = 6144B */
#define SM_A   7168
#define SM_B   (SM_A + STG * A_STG)            /* 62464 */
#define SMEM_CE (SM_B + STG * B_STG)           /* 173056 */

/* ------------------------------------------------------------------ */
__device__ __nv_bfloat16 g_Wb[(size_t)V_DIM * H_DIM];   /* 131 MB */
__device__ __nv_bfloat16 g_Ab[(size_t)NROWS * H_DIM];   /*  25 MB */
__device__ float     g_inter[2 * NSEGC * 64 * R_DIM];   /*   2 MB */
__device__ float     g_m [NSLICE * NROWS];
__device__ float     g_l [NSLICE * NROWS];
__device__ float     g_ll[NSLICE * NROWS];
__device__ long long g_off[NROWS];
__device__ int       g_lab[NROWS];
__device__ int       g_flags[NROWS];

/* ------------------------------------------------------------------ */
/* helpers                                                             */
/* ------------------------------------------------------------------ */
__device__ __forceinline__ unsigned long long pack2(float x) {
    unsigned long long r;
    asm("mov.b64 %0, {%1, %1};" : "=l"(r) : "f"(x));
    return r;
}
__device__ __forceinline__ void fma2(unsigned long long& d,
                                     unsigned long long a,
                                     unsigned long long b) {
    asm("fma.rn.f32x2 %0, %1, %2, %0;" : "+l"(d) : "l"(a), "l"(b));
}
__device__ __forceinline__ void unpack2(unsigned long long v, float& lo, float& hi) {
    asm("mov.b64 {%0, %1}, %2;" : "=f"(lo), "=f"(hi) : "l"(v));
}
__device__ __forceinline__ void mma_bf16(float* c, const uint32_t* a, const uint32_t* b) {
    asm("mma.sync.aligned.m16n8k16.row.col.f32.bf16.bf16.f32 "
        "{%0,%1,%2,%3}, {%4,%5,%6,%7}, {%8,%9}, {%0,%1,%2,%3};"
        : "+f"(c[0]), "+f"(c[1]), "+f"(c[2]), "+f"(c[3])
        : "r"(a[0]), "r"(a[1]), "r"(a[2]), "r"(a[3]), "r"(b[0]), "r"(b[1]));
}
__device__ __forceinline__ uint32_t smem_u32(const void* p) {
    uint32_t a;
    asm("{ .reg .u64 t; cvta.to.shared.u64 t, %1; cvt.u32.u64 %0, t; }"
        : "=r"(a) : "l"(p));
    return a;
}
#define CP_ASYNC16(dst, src) \
    asm volatile("cp.async.cg.shared.global [%0], [%1], 16;" \
                 :: "r"(dst), "l"(src) : "memory")
#define CP_COMMIT() asm volatile("cp.async.commit_group;" ::: "memory")
#define CP_WAIT1()  asm volatile("cp.async.wait_group 1;" ::: "memory")
#define CP_WAIT0()  asm volatile("cp.async.wait_group 0;" ::: "memory")

/* ------------------------------------------------------------------ */
/* setup: row table                                                    */
/* ------------------------------------------------------------------ */
__global__ void setup_kernel(const int* __restrict__ input_ids,
                             const int* __restrict__ attention_mask,
                             const int* __restrict__ starts,
                             const int* __restrict__ ends,
                             const int* __restrict__ math_labels,
                             const int* __restrict__ math_mask) {
    __shared__ int warpsum[8];
    __shared__ int s_rlen[2];
    int tid = threadIdx.x;

    for (int b = 0; b < 2; b++) {
        int v = 0;
        for (int s = tid; s < S_LEN; s += 256) v += attention_mask[b * S_LEN + s];
        #pragma unroll
        for (int m = 16; m; m >>= 1) v += __shfl_xor_sync(0xffffffffu, v, m);
        if ((tid & 31) == 0) warpsum[tid >> 5] = v;
        __syncthreads();
        if (tid == 0) {
            int t = 0;
            for (int w = 0; w < 8; w++) t += warpsum[w];
            s_rlen[b] = t;
        }
        __syncthreads();
    }

    for (int r = tid; r < NROWS; r += 256) {
        long long off; int lab; int fl = 0;
        if (r < 4094) {
            int b = r / 2047;
            int s = r - b * 2047;
            off = (long long)(b * S_LEN + s) * H_DIM;
            lab = input_ids[b * S_LEN + s + 1];
            int st = starts[b], en = ends[b];
            if (s >= st - 1 && s <= en - 1) fl |= 1;
            if (s >= en && s < s_rlen[b] - 1) fl |= 2;
        } else if (r < 4096) {
            off = 0; lab = 0; fl = 0;
        } else {
            int idx = r - 4096;
            int b = idx >> 10, p = idx & 1023;
            off = (long long)(b * TM_LEN + p) * H_DIM;
            lab = math_labels[b * TM_LEN + p];
            fl  = math_mask[b * TM_LEN + p] ? 4 : 0;
        }
        g_off[r] = off; g_lab[r] = lab; g_flags[r] = fl;
    }
}

/* ------------------------------------------------------------------ */
/* convW: W f32 -> bf16 (one-shot)                                     */
/* ------------------------------------------------------------------ */
__global__ __launch_bounds__(256, 2)
void convW_kernel(const float* __restrict__ W) {
    size_t i = ((size_t)blockIdx.x * 256 + threadIdx.x) * 8;
    float4 x0 = *(const float4*)(W + i);
    float4 x1 = *(const float4*)(W + i + 4);
    __nv_bfloat162 b0 = __floats2bfloat162_rn(x0.x, x0.y);
    __nv_bfloat162 b1 = __floats2bfloat162_rn(x0.z, x0.w);
    __nv_bfloat162 b2 = __floats2bfloat162_rn(x1.x, x1.y);
    __nv_bfloat162 b3 = __floats2bfloat162_rn(x1.z, x1.w);
    uint4 o;
    o.x = *(uint32_t*)&b0; o.y = *(uint32_t*)&b1;
    o.z = *(uint32_t*)&b2; o.w = *(uint32_t*)&b3;
    *(uint4*)(g_Wb + i) = o;
}

/* ------------------------------------------------------------------ */
/* convA: gather main rows from hidden -> bf16 (rows 0..4095)          */
/* ------------------------------------------------------------------ */
__global__ __launch_bounds__(256, 2)
void convA_kernel(const float* __restrict__ hidden) {
    int row = blockIdx.x;
    const float* src = hidden + g_off[row];
    int k = threadIdx.x * 8;
    float4 x0 = *(const float4*)(src + k);
    float4 x1 = *(const float4*)(src + k + 4);
    __nv_bfloat162 b0 = __floats2bfloat162_rn(x0.x, x0.y);
    __nv_bfloat162 b1 = __floats2bfloat162_rn(x0.z, x0.w);
    __nv_bfloat162 b2 = __floats2bfloat162_rn(x1.x, x1.y);
    __nv_bfloat162 b3 = __floats2bfloat162_rn(x1.z, x1.w);
    uint4 o;
    o.x = *(uint32_t*)&b0; o.y = *(uint32_t*)&b1;
    o.z = *(uint32_t*)&b2; o.w = *(uint32_t*)&b3;
    *(uint4*)(g_Ab + (size_t)row * H_DIM + k) = o;
}

/* ------------------------------------------------------------------ */
/* M1: inter = gather(hidden) @ B_seg^T  (K=2048)                      */
/* ------------------------------------------------------------------ */
__global__ __launch_bounds__(256, 1)
void m1_kernel(const float* __restrict__ hidden,
               const int*   __restrict__ starts,
               const float* __restrict__ Bm) {
    __shared__ __align__(16) float a_s[64 * 33];
    __shared__ __align__(16) float b_s[32 * 260];
    int tid = threadIdx.x;
    int b   = blockIdx.x >> 4;
    int seg = blockIdx.x & 15;
    int st  = starts[b];
    const float* abase = hidden + (long long)(b * S_LEN + st + seg * 64) * H_DIM;
    const float* bbase = Bm + (long long)seg * R_DIM * H_DIM;

    int lr = tid >> 2;
    int lk = (tid & 3) * 8;
    int row0 = (tid >> 5) * 8;
    int col0 = (tid & 31) * 8;

    unsigned long long acc[8][4];
    #pragma unroll
    for (int i = 0; i < 8; i++)
        #pragma unroll
        for (int j = 0; j < 4; j++) acc[i][j] = 0ull;

    for (int kt = 0; kt < H_DIM / 32; kt++) {
        int k0 = kt * 32;
        __syncthreads();
        {
            const float* ap = abase + (long long)lr * H_DIM + k0 + lk;
            float4 x0 = *(const float4*)ap;
            float4 x1 = *(const float4*)(ap + 4);
            float* d = a_s + lr * 33 + lk;
            d[0]=x0.x; d[1]=x0.y; d[2]=x0.z; d[3]=x0.w;
            d[4]=x1.x; d[5]=x1.y; d[6]=x1.z; d[7]=x1.w;
            #pragma unroll
            for (int q = 0; q < 4; q++) {
                int col = lr + q * 64;
                const float* bp = bbase + (long long)col * H_DIM + k0 + lk;
                float4 y0 = *(const float4*)bp;
                float4 y1 = *(const float4*)(bp + 4);
                float* e = b_s + lk * 260 + col;
                e[0*260]=y0.x; e[1*260]=y0.y; e[2*260]=y0.z; e[3*260]=y0.w;
                e[4*260]=y1.x; e[5*260]=y1.y; e[6*260]=y1.z; e[7*260]=y1.w;
            }
        }
        __syncthreads();
        #pragma unroll 8
        for (int kk = 0; kk < 32; kk++) {
            float ar[8];
            #pragma unroll
            for (int i = 0; i < 8; i++) ar[i] = a_s[(row0 + i) * 33 + kk];
            ulonglong2 wa = *(const ulonglong2*)(b_s + kk * 260 + col0);
            ulonglong2 wb = *(const ulonglong2*)(b_s + kk * 260 + col0 + 4);
            #pragma unroll
            for (int i = 0; i < 8; i++) {
                unsigned long long h = pack2(ar[i]);
                fma2(acc[i][0], h, wa.x);
                fma2(acc[i][1], h, wa.y);
                fma2(acc[i][2], h, wb.x);
                fma2(acc[i][3], h, wb.y);
            }
        }
    }
    float* out = g_inter + (long long)blockIdx.x * 64 * R_DIM;
    #pragma unroll
    for (int i = 0; i < 8; i++) {
        float v[8];
        unpack2(acc[i][0], v[0], v[1]);
        unpack2(acc[i][1], v[2], v[3]);
        unpack2(acc[i][2], v[4], v[5]);
        unpack2(acc[i][3], v[6], v[7]);
        #pragma unroll
        for (int j = 0; j < 8; j++)
            out[(row0 + i) * R_DIM + col0 + j] = v[j];
    }
}

/* ------------------------------------------------------------------ */
/* M2: A rows 4096+ = bf16(inter @ A_seg^T + bias)  (K=256)            */
/* ------------------------------------------------------------------ */
__global__ __launch_bounds__(256, 1)
void m2_kernel(const float* __restrict__ Am,
               const float* __restrict__ bias) {
    __shared__ __align__(16) float a_s[64 * 33];
    __shared__ __align__(16) float b_s[32 * 260];
    int tid = threadIdx.x;
    int bs = blockIdx.x;
    int b = bs >> 4, seg = bs & 15;
    int cb = blockIdx.y;
    const float* abase = g_inter + (long long)bs * 64 * R_DIM;
    const float* bbase = Am + ((long long)seg * H_DIM + cb * 256) * R_DIM;

    int lr = tid >> 2;
    int lk = (tid & 3) * 8;
    int row0 = (tid >> 5) * 8;
    int col0 = (tid & 31) * 8;

    unsigned long long acc[8][4];
    #pragma unroll
    for (int i = 0; i < 8; i++)
        #pragma unroll
        for (int j = 0; j < 4; j++) acc[i][j] = 0ull;

    for (int kt = 0; kt < R_DIM / 32; kt++) {
        int k0 = kt * 32;
        __syncthreads();
        {
            const float* ap = abase + (long long)lr * R_DIM + k0 + lk;
            float4 x0 = *(const float4*)ap;
            float4 x1 = *(const float4*)(ap + 4);
            float* d = a_s + lr * 33 + lk;
            d[0]=x0.x; d[1]=x0.y; d[2]=x0.z; d[3]=x0.w;
            d[4]=x1.x; d[5]=x1.y; d[6]=x1.z; d[7]=x1.w;
            #pragma unroll
            for (int q = 0; q < 4; q++) {
                int col = lr + q * 64;
                const float* bp = bbase + (long long)col * R_DIM + k0 + lk;
                float4 y0 = *(const float4*)bp;
                float4 y1 = *(const float4*)(bp + 4);
                float* e = b_s + lk * 260 + col;
                e[0*260]=y0.x; e[1*260]=y0.y; e[2*260]=y0.z; e[3*260]=y0.w;
                e[4*260]=y1.x; e[5*260]=y1.y; e[6*260]=y1.z; e[7*260]=y1.w;
            }
        }
        __syncthreads();
        #pragma unroll 8
        for (int kk = 0; kk < 32; kk++) {
            float ar[8];
            #pragma unroll
            for (int i = 0; i < 8; i++) ar[i] = a_s[(row0 + i) * 33 + kk];
            ulonglong2 wa = *(const ulonglong2*)(b_s + kk * 260 + col0);
            ulonglong2 wb = *(const ulonglong2*)(b_s + kk * 260 + col0 + 4);
            #pragma unroll
            for (int i = 0; i < 8; i++) {
                unsigned long long h = pack2(ar[i]);
                fma2(acc[i][0], h, wa.x);
                fma2(acc[i][1], h, wa.y);
                fma2(acc[i][2], h, wb.x);
                fma2(acc[i][3], h, wb.y);
            }
        }
    }
    #pragma unroll
    for (int i = 0; i < 8; i++) {
        size_t orow = (size_t)(4096 + b * TM_LEN + seg * 64 + row0 + i) * H_DIM;
        float v[8];
        unpack2(acc[i][0], v[0], v[1]);
        unpack2(acc[i][1], v[2], v[3]);
        unpack2(acc[i][2], v[4], v[5]);
        unpack2(acc[i][3], v[6], v[7]);
        #pragma unroll
        for (int j = 0; j < 8; j++) {
            int h = cb * 256 + col0 + j;
            g_Ab[orow + h] = __float2bfloat16(v[j] + bias[seg * H_DIM + h]);
        }
    }
}

/* ------------------------------------------------------------------ */
/* CE: bf16 mma.sync GEMM (CTA 128x256, warp 64x64) + online lse       */
/* ------------------------------------------------------------------ */
__global__ __launch_bounds__(256, 1)
void ce_bf16_kernel() {
    extern __shared__ __align__(16) char smem[];
    int*   s_lab = (int*)(smem + SM_LAB);
    float* s_cmb = (float*)(smem + SM_CMB);
    uint32_t sA_u = smem_u32(smem + SM_A);
    uint32_t sB_u = smem_u32(smem + SM_B);

    int tid   = threadIdx.x;
    int rb    = blockIdx.x;
    int slice = blockIdx.y;
    int wid   = tid >> 5, lane = tid & 31;
    int warp_m = wid & 1;           /* 2 warps down M: 64 rows each */
    int warp_n = wid >> 1;          /* 4 warps across N: 64 cols each */
    int g  = lane >> 2;
    int tq = lane & 3;

    if (tid < 128) s_lab[tid] = g_lab[rb * 128 + tid];
    __syncthreads();

    int labr[4][2];
    #pragma unroll
    for (int mt = 0; mt < 4; mt++)
        #pragma unroll
        for (int h = 0; h < 2; h++)
            labr[mt][h] = s_lab[warp_m * 64 + mt * 16 + h * 8 + g];

    /* loader assignment (per stage): A 4 chunks, B 8 chunks of 16B */
    const __nv_bfloat16* Abase = g_Ab + (size_t)(rb * 128) * H_DIM;
    int ar[4], aq[4];
    #pragma unroll
    for (int t = 0; t < 4; t++) {
        int idx = t * 256 + tid;
        ar[t] = idx >> 3; aq[t] = idx & 7;
    }
    int bcol[8], bq[8];
    #pragma unroll
    for (int t = 0; t < 8; t++) {
        int idx = t * 256 + tid;
        bcol[t] = idx >> 3; bq[t] = idx & 7;
    }

    int p0 = (slice * NPASS) / NSLICE;
    int p1 = ((slice + 1) * NPASS) / NSLICE;

    float m_run[4][2], l_run[4][2], ll[4][2];
    #pragma unroll
    for (int mt = 0; mt < 4; mt++)
        #pragma unroll
        for (int h = 0; h < 2; h++) {
            m_run[mt][h] = NEG_BIG; l_run[mt][h] = 0.f; ll[mt][h] = NEG_BIG;
        }

    for (int pass = p0; pass < p1; pass++) {
        int vbase = pass * BN;
        const __nv_bfloat16* Bbase = g_Wb + (size_t)vbase * H_DIM;

        float acc[4][8][4];
        #pragma unroll
        for (int mt = 0; mt < 4; mt++)
            #pragma unroll
            for (int nt = 0; nt < 8; nt++)
                #pragma unroll
                for (int j = 0; j < 4; j++) acc[mt][nt][j] = 0.f;

        auto load_stage = [&](int kc) {
            int s = kc - (kc / STG) * STG;
            uint32_t da = sA_u + (uint32_t)s * A_STG;
            uint32_t db = sB_u + (uint32_t)s * B_STG;
            int ke = kc * KC;                       /* bf16 elem offset */
            #pragma unroll
            for (int t = 0; t < 4; t++) {
                const void* src = (const void*)(Abase + (size_t)ar[t] * H_DIM + ke + aq[t] * 8);
                CP_ASYNC16(da + (uint32_t)(ar[t] * 144 + aq[t] * 16), src);
            }
            #pragma unroll
            for (int t = 0; t < 8; t++) {
                const void* src = (const void*)(Bbase + (size_t)bcol[t] * H_DIM + ke + bq[t] * 8);
                CP_ASYNC16(db + (uint32_t)(bcol[t] * 144 + bq[t] * 16), src);
            }
            CP_COMMIT();
        };

        load_stage(0);
        load_stage(1);

        for (int kc = 0; kc < NKC; kc++) {
            if (kc + 1 < NKC) CP_WAIT1(); else CP_WAIT0();
            __syncthreads();
            if (kc + 2 < NKC) load_stage(kc + 2);

            int s = kc - (kc / STG) * STG;
            const uint32_t* tA = (const uint32_t*)(smem + SM_A + s * A_STG);
            const uint32_t* tB = (const uint32_t*)(smem + SM_B + s * B_STG);

            #pragma unroll
            for (int ks = 0; ks < 4; ks++) {
                int ko = ks * 8;                    /* uint32 units (16 bf16) */
                uint32_t af[4][4];
                #pragma unroll
                for (int mt = 0; mt < 4; mt++) {
                    int u = (warp_m * 64 + mt * 16 + g) * 36 + ko + tq;
                    af[mt][0] = tA[u];
                    af[mt][1] = tA[u + 8 * 36];
                    af[mt][2] = tA[u + 4];
                    af[mt][3] = tA[u + 8 * 36 + 4];
                }
                #pragma unroll
                for (int nt = 0; nt < 8; nt++) {
                    int ub = (warp_n * 64 + nt * 8 + g) * 36 + ko + tq;
                    uint32_t bf[2];
                    bf[0] = tB[ub];
                    bf[1] = tB[ub + 4];
                    #pragma unroll
                    for (int mt = 0; mt < 4; mt++)
                        mma_bf16(acc[mt][nt], af[mt], bf);
                }
            }
        }

        /* epilogue: online logsumexp for this 256-col pass */
        #pragma unroll
        for (int mt = 0; mt < 4; mt++) {
            #pragma unroll
            for (int h = 0; h < 2; h++) {
                float cm = NEG_BIG;
                #pragma unroll
                for (int nt = 0; nt < 8; nt++) {
                    cm = fmaxf(cm, acc[mt][nt][2 * h]);
                    cm = fmaxf(cm, acc[mt][nt][2 * h + 1]);
                }
                cm = fmaxf(cm, __shfl_xor_sync(0xffffffffu, cm, 1));
                cm = fmaxf(cm, __shfl_xor_sync(0xffffffffu, cm, 2));
                float mn = fmaxf(m_run[mt][h], cm);
                float ssum = 0.f;
                int cbase = vbase + warp_n * 64 + 2 * tq;
                int lb = labr[mt][h];
                #pragma unroll
                for (int nt = 0; nt < 8; nt++) {
                    float v0 = acc[mt][nt][2 * h];
                    float v1 = acc[mt][nt][2 * h + 1];
                    ssum += __expf(v0 - mn) + __expf(v1 - mn);
                    int cc = cbase + nt * 8;
                    if (cc == lb)     ll[mt][h] = v0;
                    if (cc + 1 == lb) ll[mt][h] = v1;
                }
                ssum += __shfl_xor_sync(0xffffffffu, ssum, 1);
                ssum += __shfl_xor_sync(0xffffffffu, ssum, 2);
                l_run[mt][h] = l_run[mt][h] * __expf(m_run[mt][h] - mn) + ssum;
                m_run[mt][h] = mn;
            }
        }
        __syncthreads();   /* protect stage reuse across pass boundary */
    }

    /* combine 4 n-warps via smem, write per-slice partials */
    #pragma unroll
    for (int mt = 0; mt < 4; mt++) {
        #pragma unroll
        for (int h = 0; h < 2; h++) {
            float lv = ll[mt][h];
            lv = fmaxf(lv, __shfl_xor_sync(0xffffffffu, lv, 1));
            lv = fmaxf(lv, __shfl_xor_sync(0xffffffffu, lv, 2));
            if (tq == 0) {
                int row = warp_m * 64 + mt * 16 + h * 8 + g;
                s_cmb[(warp_n * 3 + 0) * 128 + row] = m_run[mt][h];
                s_cmb[(warp_n * 3 + 1) * 128 + row] = l_run[mt][h];
                s_cmb[(warp_n * 3 + 2) * 128 + row] = lv;
            }
        }
    }
    __syncthreads();
    if (tid < 128) {
        int row = tid;
        float m = NEG_BIG, llv = NEG_BIG;
        #pragma unroll
        for (int j = 0; j < 4; j++) {
            m   = fmaxf(m,   s_cmb[(j * 3 + 0) * 128 + row]);
            llv = fmaxf(llv, s_cmb[(j * 3 + 2) * 128 + row]);
        }
        float l = 0.f;
        #pragma unroll
        for (int j = 0; j < 4; j++)
            l += s_cmb[(j * 3 + 1) * 128 + row]
               * __expf(s_cmb[(j * 3 + 0) * 128 + row] - m);
        int grow = rb * 128 + row;
        g_m [slice * NROWS + grow] = m;
        g_l [slice * NROWS + grow] = l;
        g_ll[slice * NROWS + grow] = llv;
    }
}

/* ------------------------------------------------------------------ */
/* final: merge slices -> nll -> masked means -> 4 outputs             */
/* ------------------------------------------------------------------ */
__global__ void reduce_kernel(float* __restrict__ out, int out_size) {
    __shared__ float sred[6][8];
    int tid = threadIdx.x;
    float vals[6] = {0.f, 0.f, 0.f, 0.f, 0.f, 0.f};

    for (int r = tid; r < NROWS; r += 256) {
        int fl = g_flags[r];
        if (!fl) continue;
        float m0 = g_m[r], m1 = g_m[NROWS + r], m2 = g_m[2 * NROWS + r];
        float m = fmaxf(m0, fmaxf(m1, m2));
        float l = g_l[r] * __expf(m0 - m)
                + g_l[NROWS + r] * __expf(m1 - m)
                + g_l[2 * NROWS + r] * __expf(m2 - m);
        float llv = fmaxf(g_ll[r], fmaxf(g_ll[NROWS + r], g_ll[2 * NROWS + r]));
        float nll = m + logf(l) - llv;
        if (fl & 4) { vals[0] += nll; vals[1] += 1.f; }
        if (fl & 1) { vals[2] += nll; vals[3] += 1.f; }
        if (fl & 2) { vals[4] += nll; vals[5] += 1.f; }
    }
    #pragma unroll
    for (int k = 0; k < 6; k++) {
        float v = vals[k];
        #pragma unroll
        for (int m = 16; m; m >>= 1) v += __shfl_xor_sync(0xffffffffu, v, m);
        if ((tid & 31) == 0) sred[k][tid >> 5] = v;
    }
    __syncthreads();
    if (tid == 0) {
        float tot[6];
        #pragma unroll
        for (int k = 0; k < 6; k++) {
            float a = 0.f;
            for (int w = 0; w < 8; w++) a += sred[k][w];
            tot[k] = a;
        }
        float math_loss = tot[0] / fmaxf(tot[1], 1.f);
        float st_loss   = tot[2] / fmaxf(tot[3], 1.f);
        float fa_loss   = tot[4] / fmaxf(tot[5], 1.f);
        float total = 0.5f * math_loss + 0.5f * st_loss + 0.4f * fa_loss;
        if (out_size > 0) out[0] = total;
        if (out_size > 1) out[1] = math_loss;
        if (out_size > 2) out[2] = st_loss;
        if (out_size > 3) out[3] = fa_loss;
        for (int i = 4; i < out_size; i++) out[i] = 0.f;
    }
}

/* ------------------------------------------------------------------ */
extern "C" void kernel_launch(void* const* d_in, const int* in_sizes, int n_in,
                              void* d_out, int out_size) {
    const float* hidden   = (const float*)d_in[0];
    const int*   ids      = (const int*)d_in[1];
    const int*   amask    = (const int*)d_in[2];
    const int*   starts   = (const int*)d_in[3];
    const int*   ends     = (const int*)d_in[4];
    const int*   mlab     = (const int*)d_in[5];
    const int*   mmask    = (const int*)d_in[6];
    const float* Amat     = (const float*)d_in[8];
    const float* Bmat     = (const float*)d_in[9];
    const float* bias     = (const float*)d_in[10];
    const float* W        = (const float*)d_in[11];
    float* out = (float*)d_out;

    static int smem_set = 0;
    if (!smem_set) {
        cudaFuncSetAttribute(ce_bf16_kernel,
                             cudaFuncAttributeMaxDynamicSharedMemorySize, SMEM_CE);
        smem_set = 1;
    }

    setup_kernel<<<1, 256>>>(ids, amask, starts, ends, mlab, mmask);
    convW_kernel<<<V_DIM * H_DIM / 2048, 256>>>(W);
    convA_kernel<<<4096, 256>>>(hidden);
    m1_kernel<<<32, 256>>>(hidden, starts, Bmat);
    m2_kernel<<<dim3(32, 8), 256>>>(Amat, bias);
    ce_bf16_kernel<<<dim3(48, NSLICE), 256, SMEM_CE>>>();
    reduce_kernel<<<1, 256>>>(out, out_size);
}

// round 6
// speedup vs baseline: 7.2809x; 1.1017x over previous
#include <cuda_runtime.h>
#include <cuda_bf16.h>
#include <cstdint>

#define S_LEN  2048
#define H_DIM  2048
#define V_DIM  32000
#define NSEGC  16
#define R_DIM  256
#define TM_LEN 1024
#define NROWS  6144       /* 4094 main + 2 pad + 2048 math */
#define NSLICE 3
#define NEG_BIG (-1e30f)

/* fp8 quantization scales */
#define SCA    16.0f
#define SCW    64.0f
#define SCINV  (1.0f / (16.0f * 64.0f))

/* CE tiling: CTA 128x256, warps 2m x 4n, warp tile 64x64, fp8 k-chunk 128 */
#define BN     256
#define NPASS  125        /* V / 256 */
#define NKC    16         /* 2048 / 128 */
#define STG    3
#define A_STG  18432      /* 128 rows x 144B (128 data + 16 pad) */
#define B_STG  36864      /* 256 rows x 144B */
#define SM_LAB 0
#define SM_CMB 512
#define SM_A   7168
#define SM_B   (SM_A + STG * A_STG)
#define SMEM_CE (SM_B + STG * B_STG)     /* 173056 */

/* ------------------------------------------------------------------ */
__device__ uint8_t   g_W8[(size_t)V_DIM * H_DIM];       /* 65.5 MB */
__device__ uint8_t   g_A8[(size_t)NROWS * H_DIM];       /* 12.6 MB */
__device__ float     g_inter[2 * NSEGC * 64 * R_DIM];   /*    2 MB */
__device__ float     g_m [NSLICE * NROWS];
__device__ float     g_l [NSLICE * NROWS];
__device__ float     g_ll[NSLICE * NROWS];
__device__ long long g_off[NROWS];
__device__ int       g_lab[NROWS];
__device__ int       g_flags[NROWS];

/* ------------------------------------------------------------------ */
/* helpers                                                             */
/* ------------------------------------------------------------------ */
__device__ __forceinline__ unsigned long long pack2(float x) {
    unsigned long long r;
    asm("mov.b64 %0, {%1, %1};" : "=l"(r) : "f"(x));
    return r;
}
__device__ __forceinline__ void fma2(unsigned long long& d,
                                     unsigned long long a,
                                     unsigned long long b) {
    asm("fma.rn.f32x2 %0, %1, %2, %0;" : "+l"(d) : "l"(a), "l"(b));
}
__device__ __forceinline__ void unpack2(unsigned long long v, float& lo, float& hi) {
    asm("mov.b64 {%0, %1}, %2;" : "=f"(lo), "=f"(hi) : "l"(v));
}
/* two f32 -> packed e4m3x2; byte0 = lo, byte1 = hi */
__device__ __forceinline__ uint16_t f2e4m3x2(float lo, float hi) {
    uint16_t r;
    asm("cvt.rn.satfinite.e4m3x2.f32 %0, %1, %2;" : "=h"(r) : "f"(hi), "f"(lo));
    return r;
}
__device__ __forceinline__ void mma_fp8(float* c, const uint32_t* a,
                                        uint32_t b0, uint32_t b1) {
    asm("mma.sync.aligned.m16n8k32.row.col.f32.e4m3.e4m3.f32 "
        "{%0,%1,%2,%3}, {%4,%5,%6,%7}, {%8,%9}, {%0,%1,%2,%3};"
        : "+f"(c[0]), "+f"(c[1]), "+f"(c[2]), "+f"(c[3])
        : "r"(a[0]), "r"(a[1]), "r"(a[2]), "r"(a[3]), "r"(b0), "r"(b1));
}
#define LDSM_X4(r0, r1, r2, r3, addr) \
    asm volatile("ldmatrix.sync.aligned.m8n8.x4.shared.b16 {%0,%1,%2,%3}, [%4];" \
                 : "=r"(r0), "=r"(r1), "=r"(r2), "=r"(r3) : "r"(addr))

__device__ __forceinline__ uint32_t smem_u32(const void* p) {
    uint32_t a;
    asm("{ .reg .u64 t; cvta.to.shared.u64 t, %1; cvt.u32.u64 %0, t; }"
        : "=r"(a) : "l"(p));
    return a;
}
#define CP_ASYNC16(dst, src) \
    asm volatile("cp.async.cg.shared.global [%0], [%1], 16;" \
                 :: "r"(dst), "l"(src) : "memory")
#define CP_COMMIT() asm volatile("cp.async.commit_group;" ::: "memory")
#define CP_WAIT1()  asm volatile("cp.async.wait_group 1;" ::: "memory")
#define CP_WAIT0()  asm volatile("cp.async.wait_group 0;" ::: "memory")

/* ------------------------------------------------------------------ */
/* setup: row table                                                    */
/* ------------------------------------------------------------------ */
__global__ void setup_kernel(const int* __restrict__ input_ids,
                             const int* __restrict__ attention_mask,
                             const int* __restrict__ starts,
                             const int* __restrict__ ends,
                             const int* __restrict__ math_labels,
                             const int* __restrict__ math_mask) {
    __shared__ int warpsum[8];
    __shared__ int s_rlen[2];
    int tid = threadIdx.x;

    for (int b = 0; b < 2; b++) {
        int v = 0;
        for (int s = tid; s < S_LEN; s += 256) v += attention_mask[b * S_LEN + s];
        #pragma unroll
        for (int m = 16; m; m >>= 1) v += __shfl_xor_sync(0xffffffffu, v, m);
        if ((tid & 31) == 0) warpsum[tid >> 5] = v;
        __syncthreads();
        if (tid == 0) {
            int t = 0;
            for (int w = 0; w < 8; w++) t += warpsum[w];
            s_rlen[b] = t;
        }
        __syncthreads();
    }

    for (int r = tid; r < NROWS; r += 256) {
        long long off; int lab; int fl = 0;
        if (r < 4094) {
            int b = r / 2047;
            int s = r - b * 2047;
            off = (long long)(b * S_LEN + s) * H_DIM;
            lab = input_ids[b * S_LEN + s + 1];
            int st = starts[b], en = ends[b];
            if (s >= st - 1 && s <= en - 1) fl |= 1;
            if (s >= en && s < s_rlen[b] - 1) fl |= 2;
        } else if (r < 4096) {
            off = 0; lab = 0; fl = 0;
        } else {
            int idx = r - 4096;
            int b = idx >> 10, p = idx & 1023;
            off = (long long)(b * TM_LEN + p) * H_DIM;
            lab = math_labels[b * TM_LEN + p];
            fl  = math_mask[b * TM_LEN + p] ? 4 : 0;
        }
        g_off[r] = off; g_lab[r] = lab; g_flags[r] = fl;
    }
}

/* ------------------------------------------------------------------ */
/* convW: W f32 -> e4m3 (x SCW)                                        */
/* ------------------------------------------------------------------ */
__global__ __launch_bounds__(256, 2)
void convW_kernel(const float* __restrict__ W) {
    size_t i = ((size_t)blockIdx.x * 256 + threadIdx.x) * 8;
    float4 x0 = *(const float4*)(W + i);
    float4 x1 = *(const float4*)(W + i + 4);
    uint64_t o =  (uint64_t)f2e4m3x2(x0.x * SCW, x0.y * SCW)
               | ((uint64_t)f2e4m3x2(x0.z * SCW, x0.w * SCW) << 16)
               | ((uint64_t)f2e4m3x2(x1.x * SCW, x1.y * SCW) << 32)
               | ((uint64_t)f2e4m3x2(x1.z * SCW, x1.w * SCW) << 48);
    *(uint64_t*)(g_W8 + i) = o;
}

/* ------------------------------------------------------------------ */
/* convA: gather main rows from hidden -> e4m3 (x SCA), rows 0..4095   */
/* ------------------------------------------------------------------ */
__global__ __launch_bounds__(256, 2)
void convA_kernel(const float* __restrict__ hidden) {
    int row = blockIdx.x;
    const float* src = hidden + g_off[row];
    int k = threadIdx.x * 8;
    float4 x0 = *(const float4*)(src + k);
    float4 x1 = *(const float4*)(src + k + 4);
    uint64_t o =  (uint64_t)f2e4m3x2(x0.x * SCA, x0.y * SCA)
               | ((uint64_t)f2e4m3x2(x0.z * SCA, x0.w * SCA) << 16)
               | ((uint64_t)f2e4m3x2(x1.x * SCA, x1.y * SCA) << 32)
               | ((uint64_t)f2e4m3x2(x1.z * SCA, x1.w * SCA) << 48);
    *(uint64_t*)(g_A8 + (size_t)row * H_DIM + k) = o;
}

/* ------------------------------------------------------------------ */
/* M1: inter = gather(hidden) @ B_seg^T  (K=2048)  grid (32,4)         */
/* ------------------------------------------------------------------ */
__global__ __launch_bounds__(256, 1)
void m1_kernel(const float* __restrict__ hidden,
               const int*   __restrict__ starts,
               const float* __restrict__ Bm) {
    __shared__ __align__(16) float a_s[64 * 33];
    __shared__ __align__(16) float b_s[32 * 68];
    int tid = threadIdx.x;
    int b   = blockIdx.x >> 4;
    int seg = blockIdx.x & 15;
    int cb  = blockIdx.y;               /* 0..3 : 64-col block of R */
    int st  = starts[b];
    const float* abase = hidden + (long long)(b * S_LEN + st + seg * 64) * H_DIM;
    const float* bbase = Bm + (long long)(seg * R_DIM + cb * 64) * H_DIM;

    int lr = tid >> 2;            /* 0..63 */
    int lk = (tid & 3) * 8;       /* 0,8,16,24 */
    int row0 = (tid >> 5) * 8;    /* 8 warps x 8 rows */
    int col0 = (tid & 31) * 2;    /* 32 x 2 cols */

    unsigned long long acc[8];
    #pragma unroll
    for (int i = 0; i < 8; i++) acc[i] = 0ull;

    for (int kt = 0; kt < H_DIM / 32; kt++) {
        int k0 = kt * 32;
        __syncthreads();
        {
            const float* ap = abase + (long long)lr * H_DIM + k0 + lk;
            float4 x0 = *(const float4*)ap;
            float4 x1 = *(const float4*)(ap + 4);
            float* d = a_s + lr * 33 + lk;
            d[0]=x0.x; d[1]=x0.y; d[2]=x0.z; d[3]=x0.w;
            d[4]=x1.x; d[5]=x1.y; d[6]=x1.z; d[7]=x1.w;
            const float* bp = bbase + (long long)lr * H_DIM + k0 + lk;
            float4 y0 = *(const float4*)bp;
            float4 y1 = *(const float4*)(bp + 4);
            float* e = b_s + lk * 68 + lr;
            e[0*68]=y0.x; e[1*68]=y0.y; e[2*68]=y0.z; e[3*68]=y0.w;
            e[4*68]=y1.x; e[5*68]=y1.y; e[6*68]=y1.z; e[7*68]=y1.w;
        }
        __syncthreads();
        #pragma unroll 8
        for (int kk = 0; kk < 32; kk++) {
            unsigned long long wp = *(const unsigned long long*)(b_s + kk * 68 + col0);
            #pragma unroll
            for (int i = 0; i < 8; i++)
                fma2(acc[i], pack2(a_s[(row0 + i) * 33 + kk]), wp);
        }
    }
    float* out = g_inter + (long long)blockIdx.x * 64 * R_DIM + cb * 64;
    #pragma unroll
    for (int i = 0; i < 8; i++) {
        float v0, v1;
        unpack2(acc[i], v0, v1);
        out[(row0 + i) * R_DIM + col0]     = v0;
        out[(row0 + i) * R_DIM + col0 + 1] = v1;
    }
}

/* ------------------------------------------------------------------ */
/* M2: A rows 4096+ = e4m3((inter @ A_seg^T + bias) x SCA)  (K=256)    */
/* ------------------------------------------------------------------ */
__global__ __launch_bounds__(256, 1)
void m2_kernel(const float* __restrict__ Am,
               const float* __restrict__ bias) {
    __shared__ __align__(16) float a_s[64 * 33];
    __shared__ __align__(16) float b_s[32 * 260];
    int tid = threadIdx.x;
    int bs = blockIdx.x;
    int b = bs >> 4, seg = bs & 15;
    int cb = blockIdx.y;
    const float* abase = g_inter + (long long)bs * 64 * R_DIM;
    const float* bbase = Am + ((long long)seg * H_DIM + cb * 256) * R_DIM;

    int lr = tid >> 2;
    int lk = (tid & 3) * 8;
    int row0 = (tid >> 5) * 8;
    int col0 = (tid & 31) * 8;

    unsigned long long acc[8][4];
    #pragma unroll
    for (int i = 0; i < 8; i++)
        #pragma unroll
        for (int j = 0; j < 4; j++) acc[i][j] = 0ull;

    for (int kt = 0; kt < R_DIM / 32; kt++) {
        int k0 = kt * 32;
        __syncthreads();
        {
            const float* ap = abase + (long long)lr * R_DIM + k0 + lk;
            float4 x0 = *(const float4*)ap;
            float4 x1 = *(const float4*)(ap + 4);
            float* d = a_s + lr * 33 + lk;
            d[0]=x0.x; d[1]=x0.y; d[2]=x0.z; d[3]=x0.w;
            d[4]=x1.x; d[5]=x1.y; d[6]=x1.z; d[7]=x1.w;
            #pragma unroll
            for (int q = 0; q < 4; q++) {
                int col = lr + q * 64;
                const float* bp = bbase + (long long)col * R_DIM + k0 + lk;
                float4 y0 = *(const float4*)bp;
                float4 y1 = *(const float4*)(bp + 4);
                float* e = b_s + lk * 260 + col;
                e[0*260]=y0.x; e[1*260]=y0.y; e[2*260]=y0.z; e[3*260]=y0.w;
                e[4*260]=y1.x; e[5*260]=y1.y; e[6*260]=y1.z; e[7*260]=y1.w;
            }
        }
        __syncthreads();
        #pragma unroll 8
        for (int kk = 0; kk < 32; kk++) {
            float ar[8];
            #pragma unroll
            for (int i = 0; i < 8; i++) ar[i] = a_s[(row0 + i) * 33 + kk];
            ulonglong2 wa = *(const ulonglong2*)(b_s + kk * 260 + col0);
            ulonglong2 wb = *(const ulonglong2*)(b_s + kk * 260 + col0 + 4);
            #pragma unroll
            for (int i = 0; i < 8; i++) {
                unsigned long long h = pack2(ar[i]);
                fma2(acc[i][0], h, wa.x);
                fma2(acc[i][1], h, wa.y);
                fma2(acc[i][2], h, wb.x);
                fma2(acc[i][3], h, wb.y);
            }
        }
    }
    #pragma unroll
    for (int i = 0; i < 8; i++) {
        size_t orow = (size_t)(4096 + b * TM_LEN + seg * 64 + row0 + i) * H_DIM;
        int h0 = cb * 256 + col0;
        float v[8];
        unpack2(acc[i][0], v[0], v[1]);
        unpack2(acc[i][1], v[2], v[3]);
        unpack2(acc[i][2], v[4], v[5]);
        unpack2(acc[i][3], v[6], v[7]);
        #pragma unroll
        for (int j = 0; j < 8; j++)
            v[j] = (v[j] + bias[seg * H_DIM + h0 + j]) * SCA;
        uint64_t o =  (uint64_t)f2e4m3x2(v[0], v[1])
                   | ((uint64_t)f2e4m3x2(v[2], v[3]) << 16)
                   | ((uint64_t)f2e4m3x2(v[4], v[5]) << 32)
                   | ((uint64_t)f2e4m3x2(v[6], v[7]) << 48);
        *(uint64_t*)(g_A8 + orow + h0) = o;
    }
}

/* ------------------------------------------------------------------ */
/* CE: fp8 mma.sync GEMM (CTA 128x256, warp 64x64) + online lse        */
/* ------------------------------------------------------------------ */
__global__ __launch_bounds__(256, 1)
void ce_fp8_kernel() {
    extern __shared__ __align__(16) char smem[];
    int*   s_lab = (int*)(smem + SM_LAB);
    float* s_cmb = (float*)(smem + SM_CMB);
    uint32_t sA_u = smem_u32(smem + SM_A);
    uint32_t sB_u = smem_u32(smem + SM_B);

    int tid   = threadIdx.x;
    int rb    = blockIdx.x;
    int slice = blockIdx.y;
    int wid   = tid >> 5, lane = tid & 31;
    int warp_m = wid & 1;
    int warp_n = wid >> 1;
    int g  = lane >> 2;
    int tq = lane & 3;

    if (tid < 128) s_lab[tid] = g_lab[rb * 128 + tid];
    __syncthreads();

    int labr[4][2];
    #pragma unroll
    for (int mt = 0; mt < 4; mt++)
        #pragma unroll
        for (int h = 0; h < 2; h++)
            labr[mt][h] = s_lab[warp_m * 64 + mt * 16 + h * 8 + g];

    /* cp.async loader assignment */
    const uint8_t* Abase = g_A8 + (size_t)(rb * 128) * H_DIM;
    int ar[4], aq[4];
    #pragma unroll
    for (int t = 0; t < 4; t++) {
        int idx = t * 256 + tid;
        ar[t] = idx >> 3; aq[t] = idx & 7;
    }
    int bcol[8], bq[8];
    #pragma unroll
    for (int t = 0; t < 8; t++) {
        int idx = t * 256 + tid;
        bcol[t] = idx >> 3; bq[t] = idx & 7;
    }

    /* ldmatrix per-lane addressing */
    int a_r = lane & 15;
    int a_b = (lane >> 4) * 16;
    int b_c = (lane & 7) + ((lane >> 4) & 1) * 8;
    int b_b = ((lane >> 3) & 1) * 16;

    int p0 = (slice * NPASS) / NSLICE;
    int p1 = ((slice + 1) * NPASS) / NSLICE;

    float m_run[4][2], l_run[4][2], ll[4][2];
    #pragma unroll
    for (int mt = 0; mt < 4; mt++)
        #pragma unroll
        for (int h = 0; h < 2; h++) {
            m_run[mt][h] = NEG_BIG; l_run[mt][h] = 0.f; ll[mt][h] = NEG_BIG;
        }

    for (int pass = p0; pass < p1; pass++) {
        int vbase = pass * BN;
        const uint8_t* Bbase = g_W8 + (size_t)vbase * H_DIM;

        float acc[4][8][4];
        #pragma unroll
        for (int mt = 0; mt < 4; mt++)
            #pragma unroll
            for (int nt = 0; nt < 8; nt++)
                #pragma unroll
                for (int j = 0; j < 4; j++) acc[mt][nt][j] = 0.f;

        auto load_stage = [&](int kc) {
            int s = kc - (kc / STG) * STG;
            uint32_t da = sA_u + (uint32_t)s * A_STG;
            uint32_t db = sB_u + (uint32_t)s * B_STG;
            int kb = kc * 128;                     /* byte offset in row */
            #pragma unroll
            for (int t = 0; t < 4; t++) {
                const void* src = (const void*)(Abase + (size_t)ar[t] * H_DIM + kb + aq[t] * 16);
                CP_ASYNC16(da + (uint32_t)(ar[t] * 144 + aq[t] * 16), src);
            }
            #pragma unroll
            for (int t = 0; t < 8; t++) {
                const void* src = (const void*)(Bbase + (size_t)bcol[t] * H_DIM + kb + bq[t] * 16);
                CP_ASYNC16(db + (uint32_t)(bcol[t] * 144 + bq[t] * 16), src);
            }
            CP_COMMIT();
        };

        load_stage(0);
        load_stage(1);

        for (int kc = 0; kc < NKC; kc++) {
            if (kc + 1 < NKC) CP_WAIT1(); else CP_WAIT0();
            __syncthreads();
            if (kc + 2 < NKC) load_stage(kc + 2);

            int s = kc - (kc / STG) * STG;
            uint32_t aAddr = sA_u + (uint32_t)s * A_STG
                           + (uint32_t)((warp_m * 64 + a_r) * 144 + a_b);
            uint32_t bAddr = sB_u + (uint32_t)s * B_STG
                           + (uint32_t)((warp_n * 64 + b_c) * 144 + b_b);

            #pragma unroll
            for (int ks = 0; ks < 4; ks++) {
                int ko = ks * 32;
                uint32_t af[4][4];
                #pragma unroll
                for (int mt = 0; mt < 4; mt++)
                    LDSM_X4(af[mt][0], af[mt][1], af[mt][2], af[mt][3],
                            aAddr + mt * 16 * 144 + ko);
                #pragma unroll
                for (int p = 0; p < 4; p++) {
                    uint32_t r0, r1, r2, r3;
                    LDSM_X4(r0, r1, r2, r3, bAddr + p * 16 * 144 + ko);
                    #pragma unroll
                    for (int mt = 0; mt < 4; mt++) {
                        mma_fp8(acc[mt][2 * p],     af[mt], r0, r1);
                        mma_fp8(acc[mt][2 * p + 1], af[mt], r2, r3);
                    }
                }
            }
        }

        /* epilogue: online logsumexp for this 256-col pass (scale SCINV) */
        #pragma unroll
        for (int mt = 0; mt < 4; mt++) {
            #pragma unroll
            for (int h = 0; h < 2; h++) {
                float cm = NEG_BIG;
                #pragma unroll
                for (int nt = 0; nt < 8; nt++) {
                    cm = fmaxf(cm, acc[mt][nt][2 * h]);
                    cm = fmaxf(cm, acc[mt][nt][2 * h + 1]);
                }
                cm *= SCINV;
                cm = fmaxf(cm, __shfl_xor_sync(0xffffffffu, cm, 1));
                cm = fmaxf(cm, __shfl_xor_sync(0xffffffffu, cm, 2));
                float mn = fmaxf(m_run[mt][h], cm);
                float ssum = 0.f;
                int cbase = vbase + warp_n * 64 + 2 * tq;
                int lb = labr[mt][h];
                #pragma unroll
                for (int nt = 0; nt < 8; nt++) {
                    float v0 = acc[mt][nt][2 * h]     * SCINV;
                    float v1 = acc[mt][nt][2 * h + 1] * SCINV;
                    ssum += __expf(v0 - mn) + __expf(v1 - mn);
                    int cc = cbase + nt * 8;
                    if (cc == lb)     ll[mt][h] = v0;
                    if (cc + 1 == lb) ll[mt][h] = v1;
                }
                ssum += __shfl_xor_sync(0xffffffffu, ssum, 1);
                ssum += __shfl_xor_sync(0xffffffffu, ssum, 2);
                l_run[mt][h] = l_run[mt][h] * __expf(m_run[mt][h] - mn) + ssum;
                m_run[mt][h] = mn;
            }
        }
        __syncthreads();   /* protect stage reuse across pass boundary */
    }

    /* combine 4 n-warps via smem, write per-slice partials */
    #pragma unroll
    for (int mt = 0; mt < 4; mt++) {
        #pragma unroll
        for (int h = 0; h < 2; h++) {
            float lv = ll[mt][h];
            lv = fmaxf(lv, __shfl_xor_sync(0xffffffffu, lv, 1));
            lv = fmaxf(lv, __shfl_xor_sync(0xffffffffu, lv, 2));
            if (tq == 0) {
                int row = warp_m * 64 + mt * 16 + h * 8 + g;
                s_cmb[(warp_n * 3 + 0) * 128 + row] = m_run[mt][h];
                s_cmb[(warp_n * 3 + 1) * 128 + row] = l_run[mt][h];
                s_cmb[(warp_n * 3 + 2) * 128 + row] = lv;
            }
        }
    }
    __syncthreads();
    if (tid < 128) {
        int row = tid;
        float m = NEG_BIG, llv = NEG_BIG;
        #pragma unroll
        for (int j = 0; j < 4; j++) {
            m   = fmaxf(m,   s_cmb[(j * 3 + 0) * 128 + row]);
            llv = fmaxf(llv, s_cmb[(j * 3 + 2) * 128 + row]);
        }
        float l = 0.f;
        #pragma unroll
        for (int j = 0; j < 4; j++)
            l += s_cmb[(j * 3 + 1) * 128 + row]
               * __expf(s_cmb[(j * 3 + 0) * 128 + row] - m);
        int grow = rb * 128 + row;
        g_m [slice * NROWS + grow] = m;
        g_l [slice * NROWS + grow] = l;
        g_ll[slice * NROWS + grow] = llv;
    }
}

/* ------------------------------------------------------------------ */
/* final: merge slices -> nll -> masked means -> 4 outputs             */
/* ------------------------------------------------------------------ */
__global__ void reduce_kernel(float* __restrict__ out, int out_size) {
    __shared__ float sred[6][8];
    int tid = threadIdx.x;
    float vals[6] = {0.f, 0.f, 0.f, 0.f, 0.f, 0.f};

    for (int r = tid; r < NROWS; r += 256) {
        int fl = g_flags[r];
        if (!fl) continue;
        float m0 = g_m[r], m1 = g_m[NROWS + r], m2 = g_m[2 * NROWS + r];
        float m = fmaxf(m0, fmaxf(m1, m2));
        float l = g_l[r] * __expf(m0 - m)
                + g_l[NROWS + r] * __expf(m1 - m)
                + g_l[2 * NROWS + r] * __expf(m2 - m);
        float llv = fmaxf(g_ll[r], fmaxf(g_ll[NROWS + r], g_ll[2 * NROWS + r]));
        float nll = m + logf(l) - llv;
        if (fl & 4) { vals[0] += nll; vals[1] += 1.f; }
        if (fl & 1) { vals[2] += nll; vals[3] += 1.f; }
        if (fl & 2) { vals[4] += nll; vals[5] += 1.f; }
    }
    #pragma unroll
    for (int k = 0; k < 6; k++) {
        float v = vals[k];
        #pragma unroll
        for (int m = 16; m; m >>= 1) v += __shfl_xor_sync(0xffffffffu, v, m);
        if ((tid & 31) == 0) sred[k][tid >> 5] = v;
    }
    __syncthreads();
    if (tid == 0) {
        float tot[6];
        #pragma unroll
        for (int k = 0; k < 6; k++) {
            float a = 0.f;
            for (int w = 0; w < 8; w++) a += sred[k][w];
            tot[k] = a;
        }
        float math_loss = tot[0] / fmaxf(tot[1], 1.f);
        float st_loss   = tot[2] / fmaxf(tot[3], 1.f);
        float fa_loss   = tot[4] / fmaxf(tot[5], 1.f);
        float total = 0.5f * math_loss + 0.5f * st_loss + 0.4f * fa_loss;
        if (out_size > 0) out[0] = total;
        if (out_size > 1) out[1] = math_loss;
        if (out_size > 2) out[2] = st_loss;
        if (out_size > 3) out[3] = fa_loss;
        for (int i = 4; i < out_size; i++) out[i] = 0.f;
    }
}

/* ------------------------------------------------------------------ */
extern "C" void kernel_launch(void* const* d_in, const int* in_sizes, int n_in,
                              void* d_out, int out_size) {
    const float* hidden   = (const float*)d_in[0];
    const int*   ids      = (const int*)d_in[1];
    const int*   amask    = (const int*)d_in[2];
    const int*   starts   = (const int*)d_in[3];
    const int*   ends     = (const int*)d_in[4];
    const int*   mlab     = (const int*)d_in[5];
    const int*   mmask    = (const int*)d_in[6];
    const float* Amat     = (const float*)d_in[8];
    const float* Bmat     = (const float*)d_in[9];
    const float* bias     = (const float*)d_in[10];
    const float* W        = (const float*)d_in[11];
    float* out = (float*)d_out;

    static int smem_set = 0;
    if (!smem_set) {
        cudaFuncSetAttribute(ce_fp8_kernel,
                             cudaFuncAttributeMaxDynamicSharedMemorySize, SMEM_CE);
        smem_set = 1;
    }

    setup_kernel<<<1, 256>>>(ids, amask, starts, ends, mlab, mmask);
    convW_kernel<<<V_DIM * H_DIM / 2048, 256>>>(W);
    convA_kernel<<<4096, 256>>>(hidden);
    m1_kernel<<<dim3(32, 4), 256>>>(hidden, starts, Bmat);
    m2_kernel<<<dim3(32, 8), 256>>>(Amat, bias);
    ce_fp8_kernel<<<dim3(48, NSLICE), 256, SMEM_CE>>>();
    reduce_kernel<<<1, 256>>>(out, out_size);
}